// round 1
// baseline (speedup 1.0000x reference)
#include <cuda_runtime.h>
#include <math.h>

#define NN 50000
#define EE 400000
#define E2 (EE + NN)

// ---------------- scratch (device globals; allocation-free rule) ----------------
__device__ float g_big[EE * 320];   // emb(E*128) -> ew1(E*256) -> ew2(E*128) -> er(E*320)
__device__ float g_cls1[EE * 128];
__device__ float g_cls2[EE * 64];
__device__ float g_xi[NN * 258];
__device__ float g_xl[NN * 256];
__device__ float g_xr[NN * 256];
__device__ float g_lp[NN * 256];
__device__ float g_la[NN * 64];
__device__ float g_xout[NN * 128];
__device__ float g_xin[NN * 128];
__device__ float g_lsum[NN * 64];
__device__ float g_degs[NN];
__device__ float g_degd[NN];
__device__ float g_agg[NN * 256];
__device__ float g_h1[NN * 128];
__device__ float g_h2[NN * 128];
__device__ float g_logit[E2 * 2];
__device__ float g_alpha[E2 * 2];
__device__ float g_m[NN * 2];
__device__ float g_denom[NN * 2];

// ---------------- helpers ----------------
__device__ __forceinline__ float lrelu02(float x) { return x > 0.f ? x : 0.2f * x; }

__device__ __forceinline__ float warp_sum(float v) {
#pragma unroll
    for (int o = 16; o; o >>= 1) v += __shfl_xor_sync(0xffffffffu, v, o);
    return v;
}

__device__ __forceinline__ void atomicMaxFloat(float* addr, float value) {
    if (value >= 0.f) atomicMax((int*)addr, __float_as_int(value));
    else              atomicMin((unsigned int*)addr, __float_as_uint(value));
}

// ---------------- generic SGEMM: C = act(A[M,K] @ B[K,N] + bias) ----------------
template <int ACT>
__global__ void sgemm(const float* __restrict__ A, const float* __restrict__ B,
                      const float* __restrict__ bias, float* __restrict__ C,
                      int M, int N, int K) {
    const int BM = 128, BN = 64, BK = 16, TM = 8, TN = 4;
    __shared__ float As[BK][BM];
    __shared__ float Bs[BK][BN];
    int tid = threadIdx.x;
    int tx = tid & 15;         // 16 col-threads
    int ty = tid >> 4;         // 16 row-threads
    int rowBase = blockIdx.y * BM;
    int colBase = blockIdx.x * BN;

    float acc[TM][TN];
#pragma unroll
    for (int i = 0; i < TM; i++)
#pragma unroll
        for (int j = 0; j < TN; j++) acc[i][j] = 0.f;

    for (int k0 = 0; k0 < K; k0 += BK) {
#pragma unroll
        for (int i = 0; i < 8; i++) {          // 128*16 / 256
            int e = tid + i * 256;
            int r = e >> 4, c = e & 15;
            int gr = rowBase + r, gc = k0 + c;
            As[c][r] = (gr < M && gc < K) ? A[(size_t)gr * K + gc] : 0.f;
        }
#pragma unroll
        for (int i = 0; i < 4; i++) {          // 16*64 / 256
            int e = tid + i * 256;
            int r = e >> 6, c = e & 63;
            int gr = k0 + r, gc = colBase + c;
            Bs[r][c] = (gr < K && gc < N) ? B[(size_t)gr * N + gc] : 0.f;
        }
        __syncthreads();
#pragma unroll
        for (int k = 0; k < BK; k++) {
            float a[TM], b[TN];
#pragma unroll
            for (int i = 0; i < TM; i++) a[i] = As[k][ty * TM + i];
#pragma unroll
            for (int j = 0; j < TN; j++) b[j] = Bs[k][tx * TN + j];
#pragma unroll
            for (int i = 0; i < TM; i++)
#pragma unroll
                for (int j = 0; j < TN; j++) acc[i][j] += a[i] * b[j];
        }
        __syncthreads();
    }
#pragma unroll
    for (int i = 0; i < TM; i++) {
        int r = rowBase + ty * TM + i;
        if (r >= M) continue;
#pragma unroll
        for (int j = 0; j < TN; j++) {
            int c = colBase + tx * TN + j;
            if (c >= N) continue;
            float v = acc[i][j] + (bias ? bias[c] : 0.f);
            if (ACT == 1) v = fmaxf(v, 0.f);
            C[(size_t)r * N + c] = v;
        }
    }
}

// ---------------- stage A: zero accumulators ----------------
__global__ void k_zero_stageA() {
    int i0 = blockIdx.x * blockDim.x + threadIdx.x;
    int stride = gridDim.x * blockDim.x;
    for (int t = i0; t < NN * 128; t += stride) { g_xout[t] = 0.f; g_xin[t] = 0.f; }
    for (int t = i0; t < NN * 64; t += stride) g_lsum[t] = 0.f;
    for (int t = i0; t < NN; t += stride) { g_degs[t] = 0.f; g_degd[t] = 0.f; }
}

// scatter emb rows into per-node sums; also edge_attr sums for self-loop attr
__global__ void k_scatterA(const float* __restrict__ emb, const float* __restrict__ ea,
                           const int* __restrict__ src, const int* __restrict__ dst) {
    int w = (blockIdx.x * blockDim.x + threadIdx.x) >> 5;
    int lane = threadIdx.x & 31;
    if (w >= EE) return;
    int s = src[w], d = dst[w];
    float4 v = ((const float4*)(emb + (size_t)w * 128))[lane];
    int c = lane * 4;
    atomicAdd(&g_xout[s * 128 + c + 0], v.x);
    atomicAdd(&g_xout[s * 128 + c + 1], v.y);
    atomicAdd(&g_xout[s * 128 + c + 2], v.z);
    atomicAdd(&g_xout[s * 128 + c + 3], v.w);
    atomicAdd(&g_xin[d * 128 + c + 0], v.x);
    atomicAdd(&g_xin[d * 128 + c + 1], v.y);
    atomicAdd(&g_xin[d * 128 + c + 2], v.z);
    atomicAdd(&g_xin[d * 128 + c + 3], v.w);
    float2 e2 = ((const float2*)(ea + (size_t)w * 64))[lane];
    atomicAdd(&g_lsum[d * 64 + 2 * lane + 0], e2.x);
    atomicAdd(&g_lsum[d * 64 + 2 * lane + 1], e2.y);
    if (lane == 0) { atomicAdd(&g_degs[s], 1.f); atomicAdd(&g_degd[d], 1.f); }
}

__global__ void k_build_xi(const float* __restrict__ node_stats) {
    int i0 = blockIdx.x * blockDim.x + threadIdx.x;
    int stride = gridDim.x * blockDim.x;
    for (int t = i0; t < NN * 128; t += stride) {
        int v = t >> 7, c = t & 127;
        g_xi[(size_t)v * 258 + c] = g_xout[t] / fmaxf(g_degs[v], 1.f);
        g_xi[(size_t)v * 258 + 128 + c] = g_xin[t] / fmaxf(g_degd[v], 1.f);
    }
    for (int t = i0; t < NN * 64; t += stride) {
        int v = t >> 6;
        g_la[t] = g_lsum[t] / fmaxf(g_degd[v], 1.f);
    }
    for (int t = i0; t < NN * 2; t += stride) {
        int v = t >> 1;
        g_xi[(size_t)v * 258 + 256 + (t & 1)] = node_stats[t];
    }
}

// ---------------- GAT passes ----------------
__global__ void k_zero_gat(int H) {
    int i0 = blockIdx.x * blockDim.x + threadIdx.x;
    int stride = gridDim.x * blockDim.x;
    for (int t = i0; t < NN * H * 128; t += stride) g_agg[t] = 0.f;
    for (int t = i0; t < NN * H; t += stride) { g_denom[t] = 0.f; g_m[t] = __int_as_float(0xff800000); }
}

__global__ void k_gat_logit(const float* __restrict__ xl, const float* __restrict__ xr,
                            const float* __restrict__ ew, const float* __restrict__ lp,
                            const float* __restrict__ att, const int* __restrict__ src,
                            const int* __restrict__ dst, int H) {
    int w = (blockIdx.x * blockDim.x + threadIdx.x) >> 5;
    int lane = threadIdx.x & 31;
    if (w >= E2) return;
    int s, d; const float* ewr;
    if (w < EE) { s = src[w]; d = dst[w]; ewr = ew + (size_t)w * H * 128; }
    else { s = d = w - EE; ewr = lp + (size_t)(w - EE) * H * 128; }
    for (int h = 0; h < H; h++) {
        float4 a = ((const float4*)(xl + ((size_t)s * H + h) * 128))[lane];
        float4 b = ((const float4*)(xr + ((size_t)d * H + h) * 128))[lane];
        float4 e = ((const float4*)(ewr + (size_t)h * 128))[lane];
        float4 t = ((const float4*)(att + (size_t)h * 128))[lane];
        float part = lrelu02(a.x + b.x + e.x) * t.x + lrelu02(a.y + b.y + e.y) * t.y +
                     lrelu02(a.z + b.z + e.z) * t.z + lrelu02(a.w + b.w + e.w) * t.w;
        part = warp_sum(part);
        if (lane == 0) {
            g_logit[(size_t)w * H + h] = part;
            atomicMaxFloat(&g_m[d * H + h], part);
        }
    }
}

__global__ void k_gat_alpha(const int* __restrict__ dst, int H) {
    int idx = blockIdx.x * blockDim.x + threadIdx.x;
    if (idx >= E2 * H) return;
    int e = idx / H, h = idx - e * H;
    int d = (e < EE) ? dst[e] : (e - EE);
    float a = expf(g_logit[idx] - g_m[d * H + h]);
    g_alpha[idx] = a;
    atomicAdd(&g_denom[d * H + h], a);
}

__global__ void k_gat_agg(const float* __restrict__ xl, const int* __restrict__ src,
                          const int* __restrict__ dst, int H) {
    int w = (blockIdx.x * blockDim.x + threadIdx.x) >> 5;
    int lane = threadIdx.x & 31;
    if (w >= E2) return;
    int s, d;
    if (w < EE) { s = src[w]; d = dst[w]; }
    else { s = d = w - EE; }
    for (int h = 0; h < H; h++) {
        float coef = g_alpha[(size_t)w * H + h] / fmaxf(g_denom[d * H + h], 1e-16f);
        float4 a = ((const float4*)(xl + ((size_t)s * H + h) * 128))[lane];
        size_t base = ((size_t)d * H + h) * 128 + lane * 4;
        atomicAdd(&g_agg[base + 0], a.x * coef);
        atomicAdd(&g_agg[base + 1], a.y * coef);
        atomicAdd(&g_agg[base + 2], a.z * coef);
        atomicAdd(&g_agg[base + 3], a.w * coef);
    }
}

// mean over heads + bias, layernorm, ELU
__global__ void k_gat_final(const float* __restrict__ bias, const float* __restrict__ gam,
                            const float* __restrict__ bet, float* __restrict__ out, int H) {
    int v = (blockIdx.x * blockDim.x + threadIdx.x) >> 5;
    int lane = threadIdx.x & 31;
    if (v >= NN) return;
    float vals[4];
    int c0 = lane * 4;
    if (H == 2) {
        float4 a = ((const float4*)(g_agg + (size_t)v * 256))[lane];
        float4 b = ((const float4*)(g_agg + (size_t)v * 256 + 128))[lane];
        vals[0] = 0.5f * (a.x + b.x) + bias[c0 + 0];
        vals[1] = 0.5f * (a.y + b.y) + bias[c0 + 1];
        vals[2] = 0.5f * (a.z + b.z) + bias[c0 + 2];
        vals[3] = 0.5f * (a.w + b.w) + bias[c0 + 3];
    } else {
        float4 a = ((const float4*)(g_agg + (size_t)v * 128))[lane];
        vals[0] = a.x + bias[c0 + 0];
        vals[1] = a.y + bias[c0 + 1];
        vals[2] = a.z + bias[c0 + 2];
        vals[3] = a.w + bias[c0 + 3];
    }
    float mu = warp_sum(vals[0] + vals[1] + vals[2] + vals[3]) * (1.f / 128.f);
    float sq = 0.f;
#pragma unroll
    for (int j = 0; j < 4; j++) { float dlt = vals[j] - mu; sq += dlt * dlt; }
    float var = warp_sum(sq) * (1.f / 128.f);
    float rstd = rsqrtf(var + 1e-5f);
#pragma unroll
    for (int j = 0; j < 4; j++) {
        int c = c0 + j;
        float y = (vals[j] - mu) * rstd * gam[c] + bet[c];
        out[(size_t)v * 128 + c] = y > 0.f ? y : (expf(y) - 1.f);
    }
}

// ---------------- classifier ----------------
__global__ void k_gather_er(const float* __restrict__ h2, const float* __restrict__ ea,
                            const int* __restrict__ src, const int* __restrict__ dst,
                            float* __restrict__ er) {
    long t = (long)blockIdx.x * blockDim.x + threadIdx.x;
    if (t >= (long)EE * 320) return;
    int e = (int)(t / 320);
    int c = (int)(t - (long)e * 320);
    float v;
    if (c < 128)       v = h2[(size_t)src[e] * 128 + c];
    else if (c < 256)  v = h2[(size_t)dst[e] * 128 + (c - 128)];
    else               v = ea[(size_t)e * 64 + (c - 256)];
    er[t] = v;
}

__global__ void k_cls3(const float* __restrict__ hin, const float* __restrict__ w3,
                       const float* __restrict__ b3, float* __restrict__ out) {
    int w = (blockIdx.x * blockDim.x + threadIdx.x) >> 5;
    int lane = threadIdx.x & 31;
    if (w >= EE) return;
    float2 h = ((const float2*)(hin + (size_t)w * 64))[lane];
    float part = h.x * w3[2 * lane] + h.y * w3[2 * lane + 1];
    part = warp_sum(part);
    if (lane == 0) out[w] = part + b3[0];
}

// ---------------- host ----------------
static float* sym(const void* s) { void* p = nullptr; cudaGetSymbolAddress(&p, s); return (float*)p; }

extern "C" void kernel_launch(void* const* d_in, const int* in_sizes, int n_in,
                              void* d_out, int out_size) {
    const float* node_stats = (const float*)d_in[1];
    const int*   edge_index = (const int*)d_in[2];
    const float* edge_attr  = (const float*)d_in[3];
    const float* epw = (const float*)d_in[4];
    const float* epb = (const float*)d_in[5];
    const float* g1wl = (const float*)d_in[6];
    const float* g1wr = (const float*)d_in[7];
    const float* g1we = (const float*)d_in[8];
    const float* g1att = (const float*)d_in[9];
    const float* g1b = (const float*)d_in[10];
    const float* n1g = (const float*)d_in[11];
    const float* n1b = (const float*)d_in[12];
    const float* g2wl = (const float*)d_in[13];
    const float* g2wr = (const float*)d_in[14];
    const float* g2we = (const float*)d_in[15];
    const float* g2att = (const float*)d_in[16];
    const float* g2b = (const float*)d_in[17];
    const float* n2g = (const float*)d_in[18];
    const float* n2b = (const float*)d_in[19];
    const float* c1w = (const float*)d_in[20];
    const float* c1b = (const float*)d_in[21];
    const float* c2w = (const float*)d_in[22];
    const float* c2b = (const float*)d_in[23];
    const float* c3w = (const float*)d_in[24];
    const float* c3b = (const float*)d_in[25];

    const int* src = edge_index;
    const int* dst = edge_index + EE;

    float* p_big  = sym(g_big);
    float* p_cls1 = sym(g_cls1);
    float* p_cls2 = sym(g_cls2);
    float* p_xi   = sym(g_xi);
    float* p_xl   = sym(g_xl);
    float* p_xr   = sym(g_xr);
    float* p_lp   = sym(g_lp);
    float* p_la   = sym(g_la);

    const int T = 256;
    dim3 gEwarp((EE + 7) / 8);       // warp per edge
    dim3 gE2warp((E2 + 7) / 8);
    dim3 gNwarp((NN + 7) / 8);

    // ---- Stage A: edge MLP embedding + segment means ----
    k_zero_stageA<<<1024, T>>>();
    {
        dim3 grid((128 + 63) / 64, (EE + 127) / 128);
        sgemm<1><<<grid, T>>>(edge_attr, epw, epb, p_big, EE, 128, 64);   // emb
    }
    k_scatterA<<<gEwarp, T>>>(p_big, edge_attr, src, dst);
    k_build_xi<<<1024, T>>>(node_stats);

    // ---- GAT layer 1 (H=2, C=128) ----
    {
        dim3 g1((256 + 63) / 64, (NN + 127) / 128);
        sgemm<0><<<g1, T>>>(p_xi, g1wl, nullptr, p_xl, NN, 256, 258);
        sgemm<0><<<g1, T>>>(p_xi, g1wr, nullptr, p_xr, NN, 256, 258);
        sgemm<0><<<g1, T>>>(p_la, g1we, nullptr, p_lp, NN, 256, 64);
        dim3 g2((256 + 63) / 64, (EE + 127) / 128);
        sgemm<0><<<g2, T>>>(edge_attr, g1we, nullptr, p_big, EE, 256, 64); // ew1
    }
    k_zero_gat<<<1024, T>>>(2);
    k_gat_logit<<<gE2warp, T>>>(p_xl, p_xr, p_big, p_lp, g1att, src, dst, 2);
    k_gat_alpha<<<(E2 * 2 + T - 1) / T, T>>>(dst, 2);
    k_gat_agg<<<gE2warp, T>>>(p_xl, src, dst, 2);
    k_gat_final<<<gNwarp, T>>>(g1b, n1g, n1b, sym(g_h1), 2);

    // ---- GAT layer 2 (H=1, C=128) ----
    {
        dim3 g1((128 + 63) / 64, (NN + 127) / 128);
        sgemm<0><<<g1, T>>>(sym(g_h1), g2wl, nullptr, p_xl, NN, 128, 128);
        sgemm<0><<<g1, T>>>(sym(g_h1), g2wr, nullptr, p_xr, NN, 128, 128);
        sgemm<0><<<g1, T>>>(p_la, g2we, nullptr, p_lp, NN, 128, 64);
        dim3 g2((128 + 63) / 64, (EE + 127) / 128);
        sgemm<0><<<g2, T>>>(edge_attr, g2we, nullptr, p_big, EE, 128, 64); // ew2
    }
    k_zero_gat<<<1024, T>>>(1);
    k_gat_logit<<<gE2warp, T>>>(p_xl, p_xr, p_big, p_lp, g2att, src, dst, 1);
    k_gat_alpha<<<(E2 + T - 1) / T, T>>>(dst, 1);
    k_gat_agg<<<gE2warp, T>>>(p_xl, src, dst, 1);
    k_gat_final<<<gNwarp, T>>>(g2b, n2g, n2b, sym(g_h2), 1);

    // ---- Classifier ----
    {
        long tot = (long)EE * 320;
        k_gather_er<<<(unsigned)((tot + T - 1) / T), T>>>(sym(g_h2), edge_attr, src, dst, p_big);
        dim3 g1((128 + 63) / 64, (EE + 127) / 128);
        sgemm<1><<<g1, T>>>(p_big, c1w, c1b, p_cls1, EE, 128, 320);
        dim3 g2((64 + 63) / 64, (EE + 127) / 128);
        sgemm<1><<<g2, T>>>(p_cls1, c2w, c2b, p_cls2, EE, 64, 128);
        k_cls3<<<gEwarp, T>>>(p_cls2, c3w, c3b, (float*)d_out);
    }
}

// round 2
// speedup vs baseline: 2.4160x; 2.4160x over previous
#include <cuda_runtime.h>
#include <math.h>

#define NN 50000
#define EE 400000
#define E2 (EE + NN)
#define XI_LD 264   // padded leading dim for xi (K=258)

// ---------------- scratch (device globals; allocation-free rule) ----------------
__device__ float g_big[EE * 256 + 64];      // emb(E*128) -> ew1(E*256) -> ew2(E*128)
__device__ float g_cls1[EE * 128 + 64];
__device__ float g_cls2[EE * 64 + 64];
__device__ float g_xi[NN * XI_LD + 64];
__device__ float g_xl[NN * 256 + 64];
__device__ float g_xr[NN * 256 + 64];
__device__ float g_lp[NN * 256 + 64];
__device__ float g_la[NN * 64 + 64];
__device__ float g_xout[NN * 128];
__device__ float g_xin[NN * 128];
__device__ float g_lsum[NN * 64];
__device__ float g_degs[NN];
__device__ float g_degd[NN];
__device__ float g_agg[NN * 256];
__device__ float g_h1[NN * 128 + 64];
__device__ float g_h2[NN * 128 + 64];
__device__ float g_logit[E2 * 2];
__device__ float g_alpha[E2 * 2];
__device__ float g_m[NN * 2];
__device__ float g_denom[NN * 2];

// ---------------- helpers ----------------
__device__ __forceinline__ float lrelu02(float x) { return x > 0.f ? x : 0.2f * x; }

__device__ __forceinline__ float warp_sum(float v) {
#pragma unroll
    for (int o = 16; o; o >>= 1) v += __shfl_xor_sync(0xffffffffu, v, o);
    return v;
}

__device__ __forceinline__ void atomicMaxFloat(float* addr, float value) {
    if (value >= 0.f) atomicMax((int*)addr, __float_as_int(value));
    else              atomicMin((unsigned int*)addr, __float_as_uint(value));
}

__device__ __forceinline__ unsigned f2tf(float x) {
    unsigned u;
    asm("cvt.rna.tf32.f32 %0, %1;" : "=r"(u) : "f"(x));
    return u;
}

__device__ __forceinline__ void mma_tf32(float c[4], const unsigned a[4], const unsigned b[2]) {
    asm volatile(
        "mma.sync.aligned.m16n8k8.row.col.f32.tf32.tf32.f32 "
        "{%0,%1,%2,%3},{%4,%5,%6,%7},{%8,%9},{%0,%1,%2,%3};"
        : "+f"(c[0]), "+f"(c[1]), "+f"(c[2]), "+f"(c[3])
        : "r"(a[0]), "r"(a[1]), "r"(a[2]), "r"(a[3]), "r"(b[0]), "r"(b[1]));
}

// ---------------- TF32 tensor-core GEMM: C[M,N] = act(A[M,K] @ B[K,N] + bias) ----
// BM=128 BN=64 BK=32, 256 threads = 8 warps (4 along M x 2 along N), warp tile 32x32.
// GATHER=1: A row e is [h2[src[e]] | h2[dst[e]] | ea[e]] (K=320).
template <int ACT, int GATHER>
__global__ void gemm_tc(const float* __restrict__ A, int lda, int K,
                        const float* __restrict__ B,
                        const float* __restrict__ bias,
                        float* __restrict__ C, int M, int N,
                        const int* __restrict__ gsrc, const int* __restrict__ gdst,
                        const float* __restrict__ h2, const float* __restrict__ ea) {
    __shared__ unsigned As[128][36];  // [row][k], pad 4 -> conflict-free frag loads
    __shared__ unsigned Bs[32][72];   // [k][col], pad 8 -> conflict-free frag loads
    int tid = threadIdx.x;
    int warp = tid >> 5, lane = tid & 31;
    int wm = warp & 3, wn = warp >> 2;
    int rowBase = blockIdx.y * 128;
    int colBase = blockIdx.x * 64;
    int q = lane >> 2, r4 = lane & 3;

    float acc[2][4][4];
#pragma unroll
    for (int mt = 0; mt < 2; mt++)
#pragma unroll
        for (int nt = 0; nt < 4; nt++)
#pragma unroll
            for (int j = 0; j < 4; j++) acc[mt][nt][j] = 0.f;

    for (int k0 = 0; k0 < K; k0 += 32) {
        // load A tile (128x32)
#pragma unroll
        for (int i = 0; i < 4; i++) {
            int idx = tid + i * 256;
            int row = idx >> 3, kk = (idx & 7) * 4;
            int gk = k0 + kk;
            float4 v = make_float4(0.f, 0.f, 0.f, 0.f);
            if (GATHER) {
                int e = rowBase + row;
                const float* p;
                if (k0 < 128)      p = h2 + (size_t)gsrc[e] * 128 + gk;
                else if (k0 < 256) p = h2 + (size_t)gdst[e] * 128 + (gk - 128);
                else               p = ea + (size_t)e * 64 + (gk - 256);
                v = *(const float4*)p;
            } else {
                int gr = rowBase + row;
                if (gr < M && gk < lda) v = *(const float4*)(A + (size_t)gr * lda + gk);
            }
            uint4 t;
            t.x = f2tf(v.x); t.y = f2tf(v.y); t.z = f2tf(v.z); t.w = f2tf(v.w);
            *(uint4*)&As[row][kk] = t;
        }
        // load B tile (32x64)
#pragma unroll
        for (int i = 0; i < 2; i++) {
            int idx = tid + i * 256;
            int kk = idx >> 4, cc = (idx & 15) * 4;
            int gk = k0 + kk;
            float4 v = make_float4(0.f, 0.f, 0.f, 0.f);
            if (gk < K) v = *(const float4*)(B + (size_t)gk * N + colBase + cc);
            uint4 t;
            t.x = f2tf(v.x); t.y = f2tf(v.y); t.z = f2tf(v.z); t.w = f2tf(v.w);
            *(uint4*)&Bs[kk][cc] = t;
        }
        __syncthreads();

#pragma unroll
        for (int ks = 0; ks < 4; ks++) {
            int kb = ks * 8;
            unsigned af[2][4], bf[4][2];
#pragma unroll
            for (int mt = 0; mt < 2; mt++) {
                int r0 = wm * 32 + mt * 16 + q;
                af[mt][0] = As[r0][kb + r4];
                af[mt][1] = As[r0 + 8][kb + r4];
                af[mt][2] = As[r0][kb + r4 + 4];
                af[mt][3] = As[r0 + 8][kb + r4 + 4];
            }
#pragma unroll
            for (int nt = 0; nt < 4; nt++) {
                int c0 = wn * 32 + nt * 8 + q;
                bf[nt][0] = Bs[kb + r4][c0];
                bf[nt][1] = Bs[kb + r4 + 4][c0];
            }
#pragma unroll
            for (int mt = 0; mt < 2; mt++)
#pragma unroll
                for (int nt = 0; nt < 4; nt++) mma_tf32(acc[mt][nt], af[mt], bf[nt]);
        }
        __syncthreads();
    }

    // epilogue
#pragma unroll
    for (int mt = 0; mt < 2; mt++) {
        int gr0 = rowBase + wm * 32 + mt * 16 + q;
        int gr1 = gr0 + 8;
#pragma unroll
        for (int nt = 0; nt < 4; nt++) {
            int gc = colBase + wn * 32 + nt * 8 + r4 * 2;
            float2 bv = make_float2(0.f, 0.f);
            if (bias) bv = *(const float2*)(bias + gc);
            float o0 = acc[mt][nt][0] + bv.x, o1 = acc[mt][nt][1] + bv.y;
            float o2 = acc[mt][nt][2] + bv.x, o3 = acc[mt][nt][3] + bv.y;
            if (ACT == 1) {
                o0 = fmaxf(o0, 0.f); o1 = fmaxf(o1, 0.f);
                o2 = fmaxf(o2, 0.f); o3 = fmaxf(o3, 0.f);
            }
            if (gr0 < M) *(float2*)(C + (size_t)gr0 * N + gc) = make_float2(o0, o1);
            if (gr1 < M) *(float2*)(C + (size_t)gr1 * N + gc) = make_float2(o2, o3);
        }
    }
}

// ---------------- stage A: zero accumulators ----------------
__global__ void k_zero_stageA() {
    int i0 = blockIdx.x * blockDim.x + threadIdx.x;
    int stride = gridDim.x * blockDim.x;
    for (int t = i0; t < NN * 128; t += stride) { g_xout[t] = 0.f; g_xin[t] = 0.f; }
    for (int t = i0; t < NN * 64; t += stride) g_lsum[t] = 0.f;
    for (int t = i0; t < NN; t += stride) { g_degs[t] = 0.f; g_degd[t] = 0.f; }
}

__global__ void k_scatterA(const float* __restrict__ emb, const float* __restrict__ ea,
                           const int* __restrict__ src, const int* __restrict__ dst) {
    int w = (blockIdx.x * blockDim.x + threadIdx.x) >> 5;
    int lane = threadIdx.x & 31;
    if (w >= EE) return;
    int s = src[w], d = dst[w];
    float4 v = ((const float4*)(emb + (size_t)w * 128))[lane];
    int c = lane * 4;
    atomicAdd(&g_xout[s * 128 + c + 0], v.x);
    atomicAdd(&g_xout[s * 128 + c + 1], v.y);
    atomicAdd(&g_xout[s * 128 + c + 2], v.z);
    atomicAdd(&g_xout[s * 128 + c + 3], v.w);
    atomicAdd(&g_xin[d * 128 + c + 0], v.x);
    atomicAdd(&g_xin[d * 128 + c + 1], v.y);
    atomicAdd(&g_xin[d * 128 + c + 2], v.z);
    atomicAdd(&g_xin[d * 128 + c + 3], v.w);
    float2 e2 = ((const float2*)(ea + (size_t)w * 64))[lane];
    atomicAdd(&g_lsum[d * 64 + 2 * lane + 0], e2.x);
    atomicAdd(&g_lsum[d * 64 + 2 * lane + 1], e2.y);
    if (lane == 0) { atomicAdd(&g_degs[s], 1.f); atomicAdd(&g_degd[d], 1.f); }
}

__global__ void k_build_xi(const float* __restrict__ node_stats) {
    int i0 = blockIdx.x * blockDim.x + threadIdx.x;
    int stride = gridDim.x * blockDim.x;
    for (int t = i0; t < NN * 128; t += stride) {
        int v = t >> 7, c = t & 127;
        g_xi[(size_t)v * XI_LD + c] = g_xout[t] / fmaxf(g_degs[v], 1.f);
        g_xi[(size_t)v * XI_LD + 128 + c] = g_xin[t] / fmaxf(g_degd[v], 1.f);
    }
    for (int t = i0; t < NN * 64; t += stride) {
        int v = t >> 6;
        g_la[t] = g_lsum[t] / fmaxf(g_degd[v], 1.f);
    }
    for (int t = i0; t < NN * 8; t += stride) {   // stats + zero pad cols 258..263
        int v = t >> 3, c = t & 7;
        float val = (c < 2) ? node_stats[v * 2 + c] : 0.f;
        g_xi[(size_t)v * XI_LD + 256 + c] = val;
    }
}

// ---------------- GAT passes ----------------
__global__ void k_zero_gat(int H) {
    int i0 = blockIdx.x * blockDim.x + threadIdx.x;
    int stride = gridDim.x * blockDim.x;
    for (int t = i0; t < NN * H * 128; t += stride) g_agg[t] = 0.f;
    for (int t = i0; t < NN * H; t += stride) { g_denom[t] = 0.f; g_m[t] = __int_as_float(0xff800000); }
}

__global__ void k_gat_logit(const float* __restrict__ xl, const float* __restrict__ xr,
                            const float* __restrict__ ew, const float* __restrict__ lp,
                            const float* __restrict__ att, const int* __restrict__ src,
                            const int* __restrict__ dst, int H) {
    int w = (blockIdx.x * blockDim.x + threadIdx.x) >> 5;
    int lane = threadIdx.x & 31;
    if (w >= E2) return;
    int s, d; const float* ewr;
    if (w < EE) { s = src[w]; d = dst[w]; ewr = ew + (size_t)w * H * 128; }
    else { s = d = w - EE; ewr = lp + (size_t)(w - EE) * H * 128; }
    for (int h = 0; h < H; h++) {
        float4 a = ((const float4*)(xl + ((size_t)s * H + h) * 128))[lane];
        float4 b = ((const float4*)(xr + ((size_t)d * H + h) * 128))[lane];
        float4 e = ((const float4*)(ewr + (size_t)h * 128))[lane];
        float4 t = ((const float4*)(att + (size_t)h * 128))[lane];
        float part = lrelu02(a.x + b.x + e.x) * t.x + lrelu02(a.y + b.y + e.y) * t.y +
                     lrelu02(a.z + b.z + e.z) * t.z + lrelu02(a.w + b.w + e.w) * t.w;
        part = warp_sum(part);
        if (lane == 0) {
            g_logit[(size_t)w * H + h] = part;
            atomicMaxFloat(&g_m[d * H + h], part);
        }
    }
}

__global__ void k_gat_alpha(const int* __restrict__ dst, int H) {
    int idx = blockIdx.x * blockDim.x + threadIdx.x;
    if (idx >= E2 * H) return;
    int e = idx / H, h = idx - e * H;
    int d = (e < EE) ? dst[e] : (e - EE);
    float a = expf(g_logit[idx] - g_m[d * H + h]);
    g_alpha[idx] = a;
    atomicAdd(&g_denom[d * H + h], a);
}

__global__ void k_gat_agg(const float* __restrict__ xl, const int* __restrict__ src,
                          const int* __restrict__ dst, int H) {
    int w = (blockIdx.x * blockDim.x + threadIdx.x) >> 5;
    int lane = threadIdx.x & 31;
    if (w >= E2) return;
    int s, d;
    if (w < EE) { s = src[w]; d = dst[w]; }
    else { s = d = w - EE; }
    for (int h = 0; h < H; h++) {
        float coef = g_alpha[(size_t)w * H + h] / fmaxf(g_denom[d * H + h], 1e-16f);
        float4 a = ((const float4*)(xl + ((size_t)s * H + h) * 128))[lane];
        size_t base = ((size_t)d * H + h) * 128 + lane * 4;
        atomicAdd(&g_agg[base + 0], a.x * coef);
        atomicAdd(&g_agg[base + 1], a.y * coef);
        atomicAdd(&g_agg[base + 2], a.z * coef);
        atomicAdd(&g_agg[base + 3], a.w * coef);
    }
}

__global__ void k_gat_final(const float* __restrict__ bias, const float* __restrict__ gam,
                            const float* __restrict__ bet, float* __restrict__ out, int H) {
    int v = (blockIdx.x * blockDim.x + threadIdx.x) >> 5;
    int lane = threadIdx.x & 31;
    if (v >= NN) return;
    float vals[4];
    int c0 = lane * 4;
    if (H == 2) {
        float4 a = ((const float4*)(g_agg + (size_t)v * 256))[lane];
        float4 b = ((const float4*)(g_agg + (size_t)v * 256 + 128))[lane];
        vals[0] = 0.5f * (a.x + b.x) + bias[c0 + 0];
        vals[1] = 0.5f * (a.y + b.y) + bias[c0 + 1];
        vals[2] = 0.5f * (a.z + b.z) + bias[c0 + 2];
        vals[3] = 0.5f * (a.w + b.w) + bias[c0 + 3];
    } else {
        float4 a = ((const float4*)(g_agg + (size_t)v * 128))[lane];
        vals[0] = a.x + bias[c0 + 0];
        vals[1] = a.y + bias[c0 + 1];
        vals[2] = a.z + bias[c0 + 2];
        vals[3] = a.w + bias[c0 + 3];
    }
    float mu = warp_sum(vals[0] + vals[1] + vals[2] + vals[3]) * (1.f / 128.f);
    float sq = 0.f;
#pragma unroll
    for (int j = 0; j < 4; j++) { float dlt = vals[j] - mu; sq += dlt * dlt; }
    float var = warp_sum(sq) * (1.f / 128.f);
    float rstd = rsqrtf(var + 1e-5f);
#pragma unroll
    for (int j = 0; j < 4; j++) {
        int c = c0 + j;
        float y = (vals[j] - mu) * rstd * gam[c] + bet[c];
        out[(size_t)v * 128 + c] = y > 0.f ? y : (expf(y) - 1.f);
    }
}

// ---------------- classifier tail ----------------
__global__ void k_cls3(const float* __restrict__ hin, const float* __restrict__ w3,
                       const float* __restrict__ b3, float* __restrict__ out) {
    int w = (blockIdx.x * blockDim.x + threadIdx.x) >> 5;
    int lane = threadIdx.x & 31;
    if (w >= EE) return;
    float2 h = ((const float2*)(hin + (size_t)w * 64))[lane];
    float part = h.x * w3[2 * lane] + h.y * w3[2 * lane + 1];
    part = warp_sum(part);
    if (lane == 0) out[w] = part + b3[0];
}

// ---------------- host ----------------
static float* sym(const void* s) { void* p = nullptr; cudaGetSymbolAddress(&p, s); return (float*)p; }

extern "C" void kernel_launch(void* const* d_in, const int* in_sizes, int n_in,
                              void* d_out, int out_size) {
    const float* node_stats = (const float*)d_in[1];
    const int*   edge_index = (const int*)d_in[2];
    const float* edge_attr  = (const float*)d_in[3];
    const float* epw = (const float*)d_in[4];
    const float* epb = (const float*)d_in[5];
    const float* g1wl = (const float*)d_in[6];
    const float* g1wr = (const float*)d_in[7];
    const float* g1we = (const float*)d_in[8];
    const float* g1att = (const float*)d_in[9];
    const float* g1b = (const float*)d_in[10];
    const float* n1g = (const float*)d_in[11];
    const float* n1b = (const float*)d_in[12];
    const float* g2wl = (const float*)d_in[13];
    const float* g2wr = (const float*)d_in[14];
    const float* g2we = (const float*)d_in[15];
    const float* g2att = (const float*)d_in[16];
    const float* g2b = (const float*)d_in[17];
    const float* n2g = (const float*)d_in[18];
    const float* n2b = (const float*)d_in[19];
    const float* c1w = (const float*)d_in[20];
    const float* c1b = (const float*)d_in[21];
    const float* c2w = (const float*)d_in[22];
    const float* c2b = (const float*)d_in[23];
    const float* c3w = (const float*)d_in[24];
    const float* c3b = (const float*)d_in[25];

    const int* src = edge_index;
    const int* dst = edge_index + EE;

    float* p_big  = sym(g_big);
    float* p_cls1 = sym(g_cls1);
    float* p_cls2 = sym(g_cls2);
    float* p_xi   = sym(g_xi);
    float* p_xl   = sym(g_xl);
    float* p_xr   = sym(g_xr);
    float* p_lp   = sym(g_lp);
    float* p_la   = sym(g_la);
    float* p_h1   = sym(g_h1);
    float* p_h2   = sym(g_h2);

    const int T = 256;
    dim3 gEwarp((EE + 7) / 8);
    dim3 gE2warp((E2 + 7) / 8);
    dim3 gNwarp((NN + 7) / 8);
    const int MB_E = EE / 128;                 // 3125
    const int MB_N = (NN + 127) / 128;         // 391

    // ---- Stage A: edge MLP embedding + segment means ----
    k_zero_stageA<<<1024, T>>>();
    gemm_tc<1, 0><<<dim3(2, MB_E), T>>>(edge_attr, 64, 64, epw, epb, p_big, EE, 128,
                                        nullptr, nullptr, nullptr, nullptr);
    k_scatterA<<<gEwarp, T>>>(p_big, edge_attr, src, dst);
    k_build_xi<<<1024, T>>>(node_stats);

    // ---- GAT layer 1 (H=2, C=128) ----
    gemm_tc<0, 0><<<dim3(4, MB_N), T>>>(p_xi, XI_LD, 258, g1wl, nullptr, p_xl, NN, 256,
                                        nullptr, nullptr, nullptr, nullptr);
    gemm_tc<0, 0><<<dim3(4, MB_N), T>>>(p_xi, XI_LD, 258, g1wr, nullptr, p_xr, NN, 256,
                                        nullptr, nullptr, nullptr, nullptr);
    gemm_tc<0, 0><<<dim3(4, MB_N), T>>>(p_la, 64, 64, g1we, nullptr, p_lp, NN, 256,
                                        nullptr, nullptr, nullptr, nullptr);
    gemm_tc<0, 0><<<dim3(4, MB_E), T>>>(edge_attr, 64, 64, g1we, nullptr, p_big, EE, 256,
                                        nullptr, nullptr, nullptr, nullptr);
    k_zero_gat<<<1024, T>>>(2);
    k_gat_logit<<<gE2warp, T>>>(p_xl, p_xr, p_big, p_lp, g1att, src, dst, 2);
    k_gat_alpha<<<(E2 * 2 + T - 1) / T, T>>>(dst, 2);
    k_gat_agg<<<gE2warp, T>>>(p_xl, src, dst, 2);
    k_gat_final<<<gNwarp, T>>>(g1b, n1g, n1b, p_h1, 2);

    // ---- GAT layer 2 (H=1, C=128) ----
    gemm_tc<0, 0><<<dim3(2, MB_N), T>>>(p_h1, 128, 128, g2wl, nullptr, p_xl, NN, 128,
                                        nullptr, nullptr, nullptr, nullptr);
    gemm_tc<0, 0><<<dim3(2, MB_N), T>>>(p_h1, 128, 128, g2wr, nullptr, p_xr, NN, 128,
                                        nullptr, nullptr, nullptr, nullptr);
    gemm_tc<0, 0><<<dim3(2, MB_N), T>>>(p_la, 64, 64, g2we, nullptr, p_lp, NN, 128,
                                        nullptr, nullptr, nullptr, nullptr);
    gemm_tc<0, 0><<<dim3(2, MB_E), T>>>(edge_attr, 64, 64, g2we, nullptr, p_big, EE, 128,
                                        nullptr, nullptr, nullptr, nullptr);
    k_zero_gat<<<1024, T>>>(1);
    k_gat_logit<<<gE2warp, T>>>(p_xl, p_xr, p_big, p_lp, g2att, src, dst, 1);
    k_gat_alpha<<<(E2 + T - 1) / T, T>>>(dst, 1);
    k_gat_agg<<<gE2warp, T>>>(p_xl, src, dst, 1);
    k_gat_final<<<gNwarp, T>>>(g2b, n2g, n2b, p_h2, 1);

    // ---- Classifier: c1 with fused [h2[src]|h2[dst]|ea] gather ----
    gemm_tc<1, 1><<<dim3(2, MB_E), T>>>(nullptr, 320, 320, c1w, c1b, p_cls1, EE, 128,
                                        src, dst, p_h2, edge_attr);
    gemm_tc<1, 0><<<dim3(1, MB_E), T>>>(p_cls1, 128, 128, c2w, c2b, p_cls2, EE, 64,
                                        nullptr, nullptr, nullptr, nullptr);
    k_cls3<<<gEwarp, T>>>(p_cls2, c3w, c3b, (float*)d_out);
}

// round 3
// speedup vs baseline: 3.1735x; 1.3135x over previous
#include <cuda_runtime.h>
#include <math.h>

#define NN 50000
#define EE 400000
#define E2 (EE + NN)
#define XI_LD 264   // padded leading dim for xi (K=258)

// ---------------- scratch ----------------
__device__ float g_cls1[EE * 128 + 64];
__device__ float g_cls2[EE * 64 + 64];
__device__ float g_xi[NN * XI_LD + 64];
__device__ float g_xlr[NN * 512 + 64];   // [node][xl(H*128) | xr(H*128)]
__device__ float g_la[NN * 64 + 64];
__device__ float g_xout[NN * 128];
__device__ float g_xin[NN * 128];
__device__ float g_lsum[NN * 64];
__device__ float g_degs[NN];
__device__ float g_degd[NN];
__device__ float g_agg[NN * 256];
__device__ float g_h1[NN * 128 + 64];
__device__ float g_h2[NN * 128 + 64];
__device__ float g_logit[E2 * 2];
__device__ float g_alpha[E2 * 2];
__device__ float g_m[NN * 2];
__device__ float g_denom[NN * 2];
__device__ float g_wcat[264 * 512];

// ---------------- helpers ----------------
__device__ __forceinline__ float lrelu02(float x) { return x > 0.f ? x : 0.2f * x; }

__device__ __forceinline__ float warp_sum(float v) {
#pragma unroll
    for (int o = 16; o; o >>= 1) v += __shfl_xor_sync(0xffffffffu, v, o);
    return v;
}

__device__ __forceinline__ void atomicMaxFloat(float* addr, float value) {
    if (value >= 0.f) atomicMax((int*)addr, __float_as_int(value));
    else              atomicMin((unsigned int*)addr, __float_as_uint(value));
}

__device__ __forceinline__ void redv2(float* p, float a, float b) {
    asm volatile("red.global.add.v2.f32 [%0], {%1, %2};" :: "l"(p), "f"(a), "f"(b) : "memory");
}
__device__ __forceinline__ void redv4(float* p, float a, float b, float c, float d) {
    asm volatile("red.global.add.v4.f32 [%0], {%1, %2, %3, %4};"
                 :: "l"(p), "f"(a), "f"(b), "f"(c), "f"(d) : "memory");
}

__device__ __forceinline__ unsigned f2tf(float x) {
    unsigned u;
    asm("cvt.rna.tf32.f32 %0, %1;" : "=r"(u) : "f"(x));
    return u;
}

__device__ __forceinline__ void mma_tf32(float c[4], const unsigned a[4], const unsigned b[2]) {
    asm volatile(
        "mma.sync.aligned.m16n8k8.row.col.f32.tf32.tf32.f32 "
        "{%0,%1,%2,%3},{%4,%5,%6,%7},{%8,%9},{%0,%1,%2,%3};"
        : "+f"(c[0]), "+f"(c[1]), "+f"(c[2]), "+f"(c[3])
        : "r"(a[0]), "r"(a[1]), "r"(a[2]), "r"(a[3]), "r"(b[0]), "r"(b[1]));
}

// ---------------- generic TF32 GEMM (BM=128 BN=64 BK=32, 8 warps) ----------------
template <int ACT, int GATHER>
__global__ void gemm_tc(const float* __restrict__ A, int lda, int K,
                        const float* __restrict__ B,
                        const float* __restrict__ bias,
                        float* __restrict__ C, int M, int N,
                        const int* __restrict__ gsrc, const int* __restrict__ gdst,
                        const float* __restrict__ h2, const float* __restrict__ ea) {
    __shared__ unsigned As[128][36];
    __shared__ unsigned Bs[32][72];
    int tid = threadIdx.x;
    int warp = tid >> 5, lane = tid & 31;
    int wm = warp & 3, wn = warp >> 2;
    int rowBase = blockIdx.y * 128;
    int colBase = blockIdx.x * 64;
    int q = lane >> 2, r4 = lane & 3;

    float acc[2][4][4];
#pragma unroll
    for (int mt = 0; mt < 2; mt++)
#pragma unroll
        for (int nt = 0; nt < 4; nt++)
#pragma unroll
            for (int j = 0; j < 4; j++) acc[mt][nt][j] = 0.f;

    for (int k0 = 0; k0 < K; k0 += 32) {
#pragma unroll
        for (int i = 0; i < 4; i++) {
            int idx = tid + i * 256;
            int row = idx >> 3, kk = (idx & 7) * 4;
            int gk = k0 + kk;
            float4 v = make_float4(0.f, 0.f, 0.f, 0.f);
            if (GATHER) {
                int e = rowBase + row;
                const float* p;
                if (k0 < 128)      p = h2 + (size_t)gsrc[e] * 128 + gk;
                else if (k0 < 256) p = h2 + (size_t)gdst[e] * 128 + (gk - 128);
                else               p = ea + (size_t)e * 64 + (gk - 256);
                v = *(const float4*)p;
            } else {
                int gr = rowBase + row;
                if (gr < M && gk < lda) v = *(const float4*)(A + (size_t)gr * lda + gk);
            }
            uint4 t;
            t.x = f2tf(v.x); t.y = f2tf(v.y); t.z = f2tf(v.z); t.w = f2tf(v.w);
            *(uint4*)&As[row][kk] = t;
        }
#pragma unroll
        for (int i = 0; i < 2; i++) {
            int idx = tid + i * 256;
            int kk = idx >> 4, cc = (idx & 15) * 4;
            int gk = k0 + kk;
            float4 v = make_float4(0.f, 0.f, 0.f, 0.f);
            if (gk < K) v = *(const float4*)(B + (size_t)gk * N + colBase + cc);
            uint4 t;
            t.x = f2tf(v.x); t.y = f2tf(v.y); t.z = f2tf(v.z); t.w = f2tf(v.w);
            *(uint4*)&Bs[kk][cc] = t;
        }
        __syncthreads();
#pragma unroll
        for (int ks = 0; ks < 4; ks++) {
            int kb = ks * 8;
            unsigned af[2][4], bf[4][2];
#pragma unroll
            for (int mt = 0; mt < 2; mt++) {
                int r0 = wm * 32 + mt * 16 + q;
                af[mt][0] = As[r0][kb + r4];
                af[mt][1] = As[r0 + 8][kb + r4];
                af[mt][2] = As[r0][kb + r4 + 4];
                af[mt][3] = As[r0 + 8][kb + r4 + 4];
            }
#pragma unroll
            for (int nt = 0; nt < 4; nt++) {
                int c0 = wn * 32 + nt * 8 + q;
                bf[nt][0] = Bs[kb + r4][c0];
                bf[nt][1] = Bs[kb + r4 + 4][c0];
            }
#pragma unroll
            for (int mt = 0; mt < 2; mt++)
#pragma unroll
                for (int nt = 0; nt < 4; nt++) mma_tf32(acc[mt][nt], af[mt], bf[nt]);
        }
        __syncthreads();
    }

#pragma unroll
    for (int mt = 0; mt < 2; mt++) {
        int gr0 = rowBase + wm * 32 + mt * 16 + q;
        int gr1 = gr0 + 8;
#pragma unroll
        for (int nt = 0; nt < 4; nt++) {
            int gc = colBase + wn * 32 + nt * 8 + r4 * 2;
            float2 bv = make_float2(0.f, 0.f);
            if (bias) bv = *(const float2*)(bias + gc);
            float o0 = acc[mt][nt][0] + bv.x, o1 = acc[mt][nt][1] + bv.y;
            float o2 = acc[mt][nt][2] + bv.x, o3 = acc[mt][nt][3] + bv.y;
            if (ACT == 1) {
                o0 = fmaxf(o0, 0.f); o1 = fmaxf(o1, 0.f);
                o2 = fmaxf(o2, 0.f); o3 = fmaxf(o3, 0.f);
            }
            if (gr0 < M) *(float2*)(C + (size_t)gr0 * N + gc) = make_float2(o0, o1);
            if (gr1 < M) *(float2*)(C + (size_t)gr1 * N + gc) = make_float2(o2, o3);
        }
    }
}

// ---------------- fused emb GEMM + scatter (N=128, K=64, M=EE) ----------------
__global__ void gemm_emb_scatter(const float* __restrict__ A, const float* __restrict__ B,
                                 const float* __restrict__ bias,
                                 const int* __restrict__ src, const int* __restrict__ dst) {
    __shared__ unsigned As[128][36];
    __shared__ unsigned Bs[32][72];
    int tid = threadIdx.x;
    int warp = tid >> 5, lane = tid & 31;
    int wm = warp & 3, wn = warp >> 2;
    int rowBase = blockIdx.y * 128;
    int colBase = blockIdx.x * 64;
    int q = lane >> 2, r4 = lane & 3;

    float acc[2][4][4];
#pragma unroll
    for (int mt = 0; mt < 2; mt++)
#pragma unroll
        for (int nt = 0; nt < 4; nt++)
#pragma unroll
            for (int j = 0; j < 4; j++) acc[mt][nt][j] = 0.f;

    for (int k0 = 0; k0 < 64; k0 += 32) {
#pragma unroll
        for (int i = 0; i < 4; i++) {
            int idx = tid + i * 256;
            int row = idx >> 3, kk = (idx & 7) * 4;
            float4 v = *(const float4*)(A + (size_t)(rowBase + row) * 64 + k0 + kk);
            uint4 t;
            t.x = f2tf(v.x); t.y = f2tf(v.y); t.z = f2tf(v.z); t.w = f2tf(v.w);
            *(uint4*)&As[row][kk] = t;
        }
#pragma unroll
        for (int i = 0; i < 2; i++) {
            int idx = tid + i * 256;
            int kk = idx >> 4, cc = (idx & 15) * 4;
            float4 v = *(const float4*)(B + (size_t)(k0 + kk) * 128 + colBase + cc);
            uint4 t;
            t.x = f2tf(v.x); t.y = f2tf(v.y); t.z = f2tf(v.z); t.w = f2tf(v.w);
            *(uint4*)&Bs[kk][cc] = t;
        }
        __syncthreads();
#pragma unroll
        for (int ks = 0; ks < 4; ks++) {
            int kb = ks * 8;
            unsigned af[2][4], bf[4][2];
#pragma unroll
            for (int mt = 0; mt < 2; mt++) {
                int r0 = wm * 32 + mt * 16 + q;
                af[mt][0] = As[r0][kb + r4];
                af[mt][1] = As[r0 + 8][kb + r4];
                af[mt][2] = As[r0][kb + r4 + 4];
                af[mt][3] = As[r0 + 8][kb + r4 + 4];
            }
#pragma unroll
            for (int nt = 0; nt < 4; nt++) {
                int c0 = wn * 32 + nt * 8 + q;
                bf[nt][0] = Bs[kb + r4][c0];
                bf[nt][1] = Bs[kb + r4 + 4][c0];
            }
#pragma unroll
            for (int mt = 0; mt < 2; mt++)
#pragma unroll
                for (int nt = 0; nt < 4; nt++) mma_tf32(acc[mt][nt], af[mt], bf[nt]);
        }
        __syncthreads();
    }

#pragma unroll
    for (int mt = 0; mt < 2; mt++) {
        int gr0 = rowBase + wm * 32 + mt * 16 + q;
        int gr1 = gr0 + 8;
        int s0 = __ldg(src + gr0), d0 = __ldg(dst + gr0);
        int s1 = __ldg(src + gr1), d1 = __ldg(dst + gr1);
#pragma unroll
        for (int nt = 0; nt < 4; nt++) {
            int gc = colBase + wn * 32 + nt * 8 + r4 * 2;
            float2 bv = *(const float2*)(bias + gc);
            float v0 = fmaxf(acc[mt][nt][0] + bv.x, 0.f);
            float v1 = fmaxf(acc[mt][nt][1] + bv.y, 0.f);
            float v2 = fmaxf(acc[mt][nt][2] + bv.x, 0.f);
            float v3 = fmaxf(acc[mt][nt][3] + bv.y, 0.f);
            redv2(&g_xout[(size_t)s0 * 128 + gc], v0, v1);
            redv2(&g_xin[(size_t)d0 * 128 + gc], v0, v1);
            redv2(&g_xout[(size_t)s1 * 128 + gc], v2, v3);
            redv2(&g_xin[(size_t)d1 * 128 + gc], v2, v3);
        }
    }
}

// ---------------- fused ew GEMM + GATv2 logit ----------------
template <int H>
__global__ void k_logit_fused(const float* __restrict__ ea, const float* __restrict__ la,
                              const float* __restrict__ we, const float* __restrict__ att,
                              const float* __restrict__ xlr,
                              const int* __restrict__ src, const int* __restrict__ dst) {
    const int W = 2 * H * 128;
    const int XOFF = H * 128;
    const int NB = H * 128;
    __shared__ unsigned As[128][68];
    __shared__ unsigned Bs[32][72];
    __shared__ float sp[128][2];
    __shared__ float lg[H][128];
    int tid = threadIdx.x;
    int warp = tid >> 5, lane = tid & 31;
    int wm = warp & 3, wn = warp >> 2;
    int q = lane >> 2, r4 = lane & 3;
    int e0 = blockIdx.x * 128;

    for (int i = tid; i < H * 128; i += 256) lg[i >> 7][i & 127] = 0.f;

    // load A (128 edges x K=64) once, tf32-converted
#pragma unroll
    for (int i = 0; i < 8; i++) {
        int idx = tid + i * 256;
        int row = idx >> 4, gc = (idx & 15) * 4;
        int e = e0 + row;
        float4 v = make_float4(0.f, 0.f, 0.f, 0.f);
        if (e < EE)      v = *(const float4*)(ea + (size_t)e * 64 + gc);
        else if (e < E2) v = *(const float4*)(la + (size_t)(e - EE) * 64 + gc);
        uint4 t;
        t.x = f2tf(v.x); t.y = f2tf(v.y); t.z = f2tf(v.z); t.w = f2tf(v.w);
        *(uint4*)&As[row][gc] = t;
    }
    // per-thread row metadata (4 rows: mt x half)
    int ss[2][2], dd[2][2];
    bool vld[2][2];
#pragma unroll
    for (int mt = 0; mt < 2; mt++)
#pragma unroll
        for (int hf = 0; hf < 2; hf++) {
            int e = e0 + wm * 32 + mt * 16 + hf * 8 + q;
            bool v = e < E2;
            vld[mt][hf] = v;
            if (!v) { ss[mt][hf] = 0; dd[mt][hf] = 0; }
            else if (e < EE) { ss[mt][hf] = __ldg(src + e); dd[mt][hf] = __ldg(dst + e); }
            else { ss[mt][hf] = e - EE; dd[mt][hf] = e - EE; }
        }
    __syncthreads();

    for (int strip = 0; strip < 2 * H; strip++) {
        float acc[2][4][4];
#pragma unroll
        for (int mt = 0; mt < 2; mt++)
#pragma unroll
            for (int nt = 0; nt < 4; nt++)
#pragma unroll
                for (int j = 0; j < 4; j++) acc[mt][nt][j] = 0.f;

        for (int kt = 0; kt < 2; kt++) {
            __syncthreads();
#pragma unroll
            for (int i = 0; i < 2; i++) {
                int idx = tid + i * 256;
                int kk = idx >> 4, cc = (idx & 15) * 4;
                float4 v = *(const float4*)(we + (size_t)(kt * 32 + kk) * NB + strip * 64 + cc);
                uint4 t;
                t.x = f2tf(v.x); t.y = f2tf(v.y); t.z = f2tf(v.z); t.w = f2tf(v.w);
                *(uint4*)&Bs[kk][cc] = t;
            }
            __syncthreads();
#pragma unroll
            for (int ks = 0; ks < 4; ks++) {
                int kb = ks * 8;
                unsigned af[2][4], bf[4][2];
#pragma unroll
                for (int mt = 0; mt < 2; mt++) {
                    int r0 = wm * 32 + mt * 16 + q;
                    int ka = kt * 32 + kb;
                    af[mt][0] = As[r0][ka + r4];
                    af[mt][1] = As[r0 + 8][ka + r4];
                    af[mt][2] = As[r0][ka + r4 + 4];
                    af[mt][3] = As[r0 + 8][ka + r4 + 4];
                }
#pragma unroll
                for (int nt = 0; nt < 4; nt++) {
                    int c0 = wn * 32 + nt * 8 + q;
                    bf[nt][0] = Bs[kb + r4][c0];
                    bf[nt][1] = Bs[kb + r4 + 4][c0];
                }
#pragma unroll
                for (int mt = 0; mt < 2; mt++)
#pragma unroll
                    for (int nt = 0; nt < 4; nt++) mma_tf32(acc[mt][nt], af[mt], bf[nt]);
            }
        }

        // epilogue: leaky(ew + xl[s] + xr[d]) . att -> per-row partial sums
        int h = strip >> 1;
        float prow[2][2] = {{0.f, 0.f}, {0.f, 0.f}};
#pragma unroll
        for (int mt = 0; mt < 2; mt++) {
#pragma unroll
            for (int nt = 0; nt < 4; nt++) {
                int gc = strip * 64 + wn * 32 + nt * 8 + r4 * 2;
                int ch = gc & 127;
                float2 at = *(const float2*)(att + h * 128 + ch);
                if (vld[mt][0]) {
                    float2 xv = *(const float2*)(xlr + (size_t)ss[mt][0] * W + h * 128 + ch);
                    float2 rv = *(const float2*)(xlr + (size_t)dd[mt][0] * W + XOFF + h * 128 + ch);
                    prow[mt][0] += lrelu02(acc[mt][nt][0] + xv.x + rv.x) * at.x +
                                   lrelu02(acc[mt][nt][1] + xv.y + rv.y) * at.y;
                }
                if (vld[mt][1]) {
                    float2 xv = *(const float2*)(xlr + (size_t)ss[mt][1] * W + h * 128 + ch);
                    float2 rv = *(const float2*)(xlr + (size_t)dd[mt][1] * W + XOFF + h * 128 + ch);
                    prow[mt][1] += lrelu02(acc[mt][nt][2] + xv.x + rv.x) * at.x +
                                   lrelu02(acc[mt][nt][3] + xv.y + rv.y) * at.y;
                }
            }
        }
#pragma unroll
        for (int mt = 0; mt < 2; mt++)
#pragma unroll
            for (int hf = 0; hf < 2; hf++) {
                float p = prow[mt][hf];
                p += __shfl_xor_sync(0xffffffffu, p, 1);
                p += __shfl_xor_sync(0xffffffffu, p, 2);
                if (r4 == 0) sp[wm * 32 + mt * 16 + hf * 8 + q][wn] = p;
            }
        __syncthreads();
        if (tid < 128) lg[h][tid] += sp[tid][0] + sp[tid][1];
    }
    __syncthreads();
    if (tid < 128) {
        int e = e0 + tid;
        if (e < E2) {
            int d = (e < EE) ? __ldg(dst + e) : (e - EE);
#pragma unroll
            for (int h = 0; h < H; h++) {
                float v = lg[h][tid];
                g_logit[(size_t)e * H + h] = v;
                atomicMaxFloat(&g_m[d * H + h], v);
            }
        }
    }
}

// ---------------- small kernels ----------------
__global__ void k_zero_stageA() {
    int i0 = blockIdx.x * blockDim.x + threadIdx.x;
    int stride = gridDim.x * blockDim.x;
    for (int t = i0; t < NN * 128; t += stride) { g_xout[t] = 0.f; g_xin[t] = 0.f; }
    for (int t = i0; t < NN * 64; t += stride) g_lsum[t] = 0.f;
    for (int t = i0; t < NN; t += stride) { g_degs[t] = 0.f; g_degd[t] = 0.f; }
}

__global__ void k_ea_sums(const float* __restrict__ ea, const int* __restrict__ src,
                          const int* __restrict__ dst) {
    int w = (blockIdx.x * blockDim.x + threadIdx.x) >> 5;
    int lane = threadIdx.x & 31;
    if (w >= EE) return;
    int s = src[w], d = dst[w];
    float2 e2 = ((const float2*)(ea + (size_t)w * 64))[lane];
    redv2(&g_lsum[(size_t)d * 64 + 2 * lane], e2.x, e2.y);
    if (lane == 0) { atomicAdd(&g_degs[s], 1.f); atomicAdd(&g_degd[d], 1.f); }
}

__global__ void k_build_xi(const float* __restrict__ node_stats) {
    int i0 = blockIdx.x * blockDim.x + threadIdx.x;
    int stride = gridDim.x * blockDim.x;
    for (int t = i0; t < NN * 128; t += stride) {
        int v = t >> 7, c = t & 127;
        g_xi[(size_t)v * XI_LD + c] = g_xout[t] / fmaxf(g_degs[v], 1.f);
        g_xi[(size_t)v * XI_LD + 128 + c] = g_xin[t] / fmaxf(g_degd[v], 1.f);
    }
    for (int t = i0; t < NN * 64; t += stride) {
        int v = t >> 6;
        g_la[t] = g_lsum[t] / fmaxf(g_degd[v], 1.f);
    }
    for (int t = i0; t < NN * 8; t += stride) {
        int v = t >> 3, c = t & 7;
        g_xi[(size_t)v * XI_LD + 256 + c] = (c < 2) ? node_stats[v * 2 + c] : 0.f;
    }
}

__global__ void k_catw(const float* __restrict__ wl, const float* __restrict__ wr,
                       int K, int N1) {
    int i = blockIdx.x * blockDim.x + threadIdx.x;
    int tot = K * 2 * N1;
    if (i >= tot) return;
    int k = i / (2 * N1), j = i - k * 2 * N1;
    g_wcat[i] = (j < N1) ? wl[k * N1 + j] : wr[k * N1 + (j - N1)];
}

__global__ void k_zero_gat(int H) {
    int i0 = blockIdx.x * blockDim.x + threadIdx.x;
    int stride = gridDim.x * blockDim.x;
    for (int t = i0; t < NN * H * 128; t += stride) g_agg[t] = 0.f;
    for (int t = i0; t < NN * H; t += stride) { g_denom[t] = 0.f; g_m[t] = __int_as_float(0xff800000); }
}

__global__ void k_gat_alpha(const int* __restrict__ dst, int H) {
    int idx = blockIdx.x * blockDim.x + threadIdx.x;
    if (idx >= E2 * H) return;
    int e = idx / H, h = idx - e * H;
    int d = (e < EE) ? dst[e] : (e - EE);
    float a = expf(g_logit[idx] - g_m[d * H + h]);
    g_alpha[idx] = a;
    atomicAdd(&g_denom[d * H + h], a);
}

__global__ void k_gat_agg(const float* __restrict__ xlr, int W, const int* __restrict__ src,
                          const int* __restrict__ dst, int H) {
    int w = (blockIdx.x * blockDim.x + threadIdx.x) >> 5;
    int lane = threadIdx.x & 31;
    if (w >= E2) return;
    int s, d;
    if (w < EE) { s = src[w]; d = dst[w]; }
    else { s = d = w - EE; }
    for (int h = 0; h < H; h++) {
        float coef = g_alpha[(size_t)w * H + h] / fmaxf(g_denom[d * H + h], 1e-16f);
        float4 a = ((const float4*)(xlr + (size_t)s * W + h * 128))[lane];
        redv4(&g_agg[((size_t)d * H + h) * 128 + lane * 4],
              a.x * coef, a.y * coef, a.z * coef, a.w * coef);
    }
}

__global__ void k_gat_final(const float* __restrict__ bias, const float* __restrict__ gam,
                            const float* __restrict__ bet, float* __restrict__ out, int H) {
    int v = (blockIdx.x * blockDim.x + threadIdx.x) >> 5;
    int lane = threadIdx.x & 31;
    if (v >= NN) return;
    float vals[4];
    int c0 = lane * 4;
    if (H == 2) {
        float4 a = ((const float4*)(g_agg + (size_t)v * 256))[lane];
        float4 b = ((const float4*)(g_agg + (size_t)v * 256 + 128))[lane];
        vals[0] = 0.5f * (a.x + b.x) + bias[c0 + 0];
        vals[1] = 0.5f * (a.y + b.y) + bias[c0 + 1];
        vals[2] = 0.5f * (a.z + b.z) + bias[c0 + 2];
        vals[3] = 0.5f * (a.w + b.w) + bias[c0 + 3];
    } else {
        float4 a = ((const float4*)(g_agg + (size_t)v * 128))[lane];
        vals[0] = a.x + bias[c0 + 0];
        vals[1] = a.y + bias[c0 + 1];
        vals[2] = a.z + bias[c0 + 2];
        vals[3] = a.w + bias[c0 + 3];
    }
    float mu = warp_sum(vals[0] + vals[1] + vals[2] + vals[3]) * (1.f / 128.f);
    float sq = 0.f;
#pragma unroll
    for (int j = 0; j < 4; j++) { float dlt = vals[j] - mu; sq += dlt * dlt; }
    float var = warp_sum(sq) * (1.f / 128.f);
    float rstd = rsqrtf(var + 1e-5f);
#pragma unroll
    for (int j = 0; j < 4; j++) {
        int c = c0 + j;
        float y = (vals[j] - mu) * rstd * gam[c] + bet[c];
        out[(size_t)v * 128 + c] = y > 0.f ? y : (expf(y) - 1.f);
    }
}

__global__ void k_cls3(const float* __restrict__ hin, const float* __restrict__ w3,
                       const float* __restrict__ b3, float* __restrict__ out) {
    int w = (blockIdx.x * blockDim.x + threadIdx.x) >> 5;
    int lane = threadIdx.x & 31;
    if (w >= EE) return;
    float2 h = ((const float2*)(hin + (size_t)w * 64))[lane];
    float part = h.x * w3[2 * lane] + h.y * w3[2 * lane + 1];
    part = warp_sum(part);
    if (lane == 0) out[w] = part + b3[0];
}

// ---------------- host ----------------
static float* sym(const void* s) { void* p = nullptr; cudaGetSymbolAddress(&p, s); return (float*)p; }

extern "C" void kernel_launch(void* const* d_in, const int* in_sizes, int n_in,
                              void* d_out, int out_size) {
    const float* node_stats = (const float*)d_in[1];
    const int*   edge_index = (const int*)d_in[2];
    const float* edge_attr  = (const float*)d_in[3];
    const float* epw = (const float*)d_in[4];
    const float* epb = (const float*)d_in[5];
    const float* g1wl = (const float*)d_in[6];
    const float* g1wr = (const float*)d_in[7];
    const float* g1we = (const float*)d_in[8];
    const float* g1att = (const float*)d_in[9];
    const float* g1b = (const float*)d_in[10];
    const float* n1g = (const float*)d_in[11];
    const float* n1b = (const float*)d_in[12];
    const float* g2wl = (const float*)d_in[13];
    const float* g2wr = (const float*)d_in[14];
    const float* g2we = (const float*)d_in[15];
    const float* g2att = (const float*)d_in[16];
    const float* g2b = (const float*)d_in[17];
    const float* n2g = (const float*)d_in[18];
    const float* n2b = (const float*)d_in[19];
    const float* c1w = (const float*)d_in[20];
    const float* c1b = (const float*)d_in[21];
    const float* c2w = (const float*)d_in[22];
    const float* c2b = (const float*)d_in[23];
    const float* c3w = (const float*)d_in[24];
    const float* c3b = (const float*)d_in[25];

    const int* src = edge_index;
    const int* dst = edge_index + EE;

    float* p_cls1 = sym(g_cls1);
    float* p_cls2 = sym(g_cls2);
    float* p_xi   = sym(g_xi);
    float* p_xlr  = sym(g_xlr);
    float* p_la   = sym(g_la);
    float* p_h1   = sym(g_h1);
    float* p_h2   = sym(g_h2);
    float* p_wcat = sym(g_wcat);

    const int T = 256;
    dim3 gEwarp((EE + 7) / 8);
    dim3 gE2warp((E2 + 7) / 8);
    dim3 gNwarp((NN + 7) / 8);
    const int MB_E = EE / 128;                 // 3125
    const int MB_N = (NN + 127) / 128;         // 391
    const int NB_L = (E2 + 127) / 128;         // 3516

    // ---- Stage A: fused edge-MLP + scatter, then xi ----
    k_zero_stageA<<<1024, T>>>();
    gemm_emb_scatter<<<dim3(2, MB_E), T>>>(edge_attr, epw, epb, src, dst);
    k_ea_sums<<<gEwarp, T>>>(edge_attr, src, dst);
    k_build_xi<<<1024, T>>>(node_stats);

    // ---- GAT layer 1 (H=2) ----
    k_catw<<<(258 * 512 + T - 1) / T, T>>>(g1wl, g1wr, 258, 256);
    gemm_tc<0, 0><<<dim3(8, MB_N), T>>>(p_xi, XI_LD, 258, p_wcat, nullptr, p_xlr, NN, 512,
                                        nullptr, nullptr, nullptr, nullptr);
    k_zero_gat<<<1024, T>>>(2);
    k_logit_fused<2><<<NB_L, T>>>(edge_attr, p_la, g1we, g1att, p_xlr, src, dst);
    k_gat_alpha<<<(E2 * 2 + T - 1) / T, T>>>(dst, 2);
    k_gat_agg<<<gE2warp, T>>>(p_xlr, 512, src, dst, 2);
    k_gat_final<<<gNwarp, T>>>(g1b, n1g, n1b, p_h1, 2);

    // ---- GAT layer 2 (H=1) ----
    k_catw<<<(128 * 256 + T - 1) / T, T>>>(g2wl, g2wr, 128, 128);
    gemm_tc<0, 0><<<dim3(4, MB_N), T>>>(p_h1, 128, 128, p_wcat, nullptr, p_xlr, NN, 256,
                                        nullptr, nullptr, nullptr, nullptr);
    k_zero_gat<<<1024, T>>>(1);
    k_logit_fused<1><<<NB_L, T>>>(edge_attr, p_la, g2we, g2att, p_xlr, src, dst);
    k_gat_alpha<<<(E2 + T - 1) / T, T>>>(dst, 1);
    k_gat_agg<<<gE2warp, T>>>(p_xlr, 256, src, dst, 1);
    k_gat_final<<<gNwarp, T>>>(g2b, n2g, n2b, p_h2, 1);

    // ---- Classifier ----
    gemm_tc<1, 1><<<dim3(2, MB_E), T>>>(nullptr, 320, 320, c1w, c1b, p_cls1, EE, 128,
                                        src, dst, p_h2, edge_attr);
    gemm_tc<1, 0><<<dim3(1, MB_E), T>>>(p_cls1, 128, 128, c2w, c2b, p_cls2, EE, 64,
                                        nullptr, nullptr, nullptr, nullptr);
    k_cls3<<<gEwarp, T>>>(p_cls2, c3w, c3b, (float*)d_out);
}

// round 4
// speedup vs baseline: 3.3458x; 1.0543x over previous
#include <cuda_runtime.h>
#include <math.h>

#define NN 50000
#define EE 400000
#define E2 (EE + NN)
#define XI_LD 264   // padded leading dim for xi (K=258)

// ---------------- scratch ----------------
__device__ float g_cls1[EE * 128 + 64];
__device__ float g_xi[NN * XI_LD + 64];
__device__ float g_xlr[NN * 512 + 64];   // [node][xl(H*128) | xr(H*128)]
__device__ float g_la[NN * 64 + 64];
__device__ float g_xout[NN * 128];
__device__ float g_xin[NN * 128];
__device__ float g_lsum[NN * 64];
__device__ float g_degs[NN];
__device__ float g_degd[NN];
__device__ float g_agg[NN * 256];
__device__ float g_h1[NN * 128 + 64];
__device__ float g_h2[NN * 128 + 64];
__device__ float g_logit[E2 * 2];
__device__ float g_m[NN * 2];
__device__ float g_denom[NN * 2];
__device__ float g_wcat[264 * 512];

// ---------------- helpers ----------------
__device__ __forceinline__ float lrelu02(float x) { return x > 0.f ? x : 0.2f * x; }

__device__ __forceinline__ float warp_sum(float v) {
#pragma unroll
    for (int o = 16; o; o >>= 1) v += __shfl_xor_sync(0xffffffffu, v, o);
    return v;
}

__device__ __forceinline__ void atomicMaxFloat(float* addr, float value) {
    if (value >= 0.f) atomicMax((int*)addr, __float_as_int(value));
    else              atomicMin((unsigned int*)addr, __float_as_uint(value));
}

__device__ __forceinline__ void redv2(float* p, float a, float b) {
    asm volatile("red.global.add.v2.f32 [%0], {%1, %2};" :: "l"(p), "f"(a), "f"(b) : "memory");
}
__device__ __forceinline__ void redv4(float* p, float a, float b, float c, float d) {
    asm volatile("red.global.add.v4.f32 [%0], {%1, %2, %3, %4};"
                 :: "l"(p), "f"(a), "f"(b), "f"(c), "f"(d) : "memory");
}

__device__ __forceinline__ unsigned f2tf(float x) {
    unsigned u;
    asm("cvt.rna.tf32.f32 %0, %1;" : "=r"(u) : "f"(x));
    return u;
}

__device__ __forceinline__ void mma_tf32(float c[4], const unsigned a[4], const unsigned b[2]) {
    asm volatile(
        "mma.sync.aligned.m16n8k8.row.col.f32.tf32.tf32.f32 "
        "{%0,%1,%2,%3},{%4,%5,%6,%7},{%8,%9},{%0,%1,%2,%3};"
        : "+f"(c[0]), "+f"(c[1]), "+f"(c[2]), "+f"(c[3])
        : "r"(a[0]), "r"(a[1]), "r"(a[2]), "r"(a[3]), "r"(b[0]), "r"(b[1]));
}

// ======== wide TF32 GEMM: BM=128 BN=128 BK=32, 512 threads (16 warps 4x4) ========
// EPI: 0 = store C (+relu if ACT), 1 = emb scatter + ea sums (no C store)
template <int ACT, int GATHER, int EPI>
__global__ __launch_bounds__(512, 1)
void gemm128(const float* __restrict__ A, int lda, int K,
             const float* __restrict__ B,
             const float* __restrict__ bias,
             float* __restrict__ C, int M, int N,
             const int* __restrict__ gsrc, const int* __restrict__ gdst,
             const float* __restrict__ h2, const float* __restrict__ ea) {
    __shared__ unsigned As[128][36];
    __shared__ unsigned Bs[32][136];
    int tid = threadIdx.x;
    int warp = tid >> 5, lane = tid & 31;
    int wm = warp & 3, wn = warp >> 2;   // 4 x 4 warps
    int rowBase = blockIdx.y * 128;
    int colBase = blockIdx.x * 128;
    int q = lane >> 2, r4 = lane & 3;

    float acc[2][4][4];
#pragma unroll
    for (int mt = 0; mt < 2; mt++)
#pragma unroll
        for (int nt = 0; nt < 4; nt++)
#pragma unroll
            for (int j = 0; j < 4; j++) acc[mt][nt][j] = 0.f;

    float4 pa[2], pb[2];

    auto loadA = [&](int k0) {
#pragma unroll
        for (int i = 0; i < 2; i++) {
            int idx = tid + i * 512;
            int row = idx >> 3, kk = (idx & 7) * 4;
            int gk = k0 + kk;
            float4 v = make_float4(0.f, 0.f, 0.f, 0.f);
            if (GATHER) {
                int e = rowBase + row;
                const float* p;
                if (k0 < 128)      p = h2 + (size_t)gsrc[e] * 128 + gk;
                else if (k0 < 256) p = h2 + (size_t)gdst[e] * 128 + (gk - 128);
                else               p = ea + (size_t)e * 64 + (gk - 256);
                v = *(const float4*)p;
            } else {
                int gr = rowBase + row;
                if (gr < M && gk < lda) v = *(const float4*)(A + (size_t)gr * lda + gk);
            }
            pa[i] = v;
        }
    };
    auto loadB = [&](int k0) {
#pragma unroll
        for (int i = 0; i < 2; i++) {
            int idx = tid + i * 512;
            int kk = idx >> 5, cc = (idx & 31) * 4;
            int gk = k0 + kk;
            float4 v = make_float4(0.f, 0.f, 0.f, 0.f);
            if (gk < K) v = *(const float4*)(B + (size_t)gk * N + colBase + cc);
            pb[i] = v;
        }
    };
    auto stsAB = [&]() {
#pragma unroll
        for (int i = 0; i < 2; i++) {
            int idx = tid + i * 512;
            int row = idx >> 3, kk = (idx & 7) * 4;
            uint4 t;
            t.x = f2tf(pa[i].x); t.y = f2tf(pa[i].y); t.z = f2tf(pa[i].z); t.w = f2tf(pa[i].w);
            *(uint4*)&As[row][kk] = t;
            int kb = idx >> 5, cc = (idx & 31) * 4;
            uint4 u;
            u.x = f2tf(pb[i].x); u.y = f2tf(pb[i].y); u.z = f2tf(pb[i].z); u.w = f2tf(pb[i].w);
            *(uint4*)&Bs[kb][cc] = u;
        }
    };

    loadA(0); loadB(0);
    for (int k0 = 0; k0 < K; k0 += 32) {
        stsAB();
        __syncthreads();
        if (k0 + 32 < K) { loadA(k0 + 32); loadB(k0 + 32); }
#pragma unroll
        for (int ks = 0; ks < 4; ks++) {
            int kb = ks * 8;
            unsigned af[2][4], bf[4][2];
#pragma unroll
            for (int mt = 0; mt < 2; mt++) {
                int r0 = wm * 32 + mt * 16 + q;
                af[mt][0] = As[r0][kb + r4];
                af[mt][1] = As[r0 + 8][kb + r4];
                af[mt][2] = As[r0][kb + r4 + 4];
                af[mt][3] = As[r0 + 8][kb + r4 + 4];
            }
#pragma unroll
            for (int nt = 0; nt < 4; nt++) {
                int c0 = wn * 32 + nt * 8 + q;
                bf[nt][0] = Bs[kb + r4][c0];
                bf[nt][1] = Bs[kb + r4 + 4][c0];
            }
#pragma unroll
            for (int mt = 0; mt < 2; mt++)
#pragma unroll
                for (int nt = 0; nt < 4; nt++) mma_tf32(acc[mt][nt], af[mt], bf[nt]);
        }
        __syncthreads();
    }

    if (EPI == 0) {
#pragma unroll
        for (int mt = 0; mt < 2; mt++) {
            int gr0 = rowBase + wm * 32 + mt * 16 + q;
            int gr1 = gr0 + 8;
#pragma unroll
            for (int nt = 0; nt < 4; nt++) {
                int gc = colBase + wn * 32 + nt * 8 + r4 * 2;
                float2 bv = make_float2(0.f, 0.f);
                if (bias) bv = *(const float2*)(bias + gc);
                float o0 = acc[mt][nt][0] + bv.x, o1 = acc[mt][nt][1] + bv.y;
                float o2 = acc[mt][nt][2] + bv.x, o3 = acc[mt][nt][3] + bv.y;
                if (ACT == 1) {
                    o0 = fmaxf(o0, 0.f); o1 = fmaxf(o1, 0.f);
                    o2 = fmaxf(o2, 0.f); o3 = fmaxf(o3, 0.f);
                }
                if (gr0 < M) *(float2*)(C + (size_t)gr0 * N + gc) = make_float2(o0, o1);
                if (gr1 < M) *(float2*)(C + (size_t)gr1 * N + gc) = make_float2(o2, o3);
            }
        }
    } else {
        // emb scatter: relu(acc+bias) -> xout[src], xin[dst]; cols = gc (N=128, colBase=0)
#pragma unroll
        for (int mt = 0; mt < 2; mt++) {
            int gr0 = rowBase + wm * 32 + mt * 16 + q;
            int gr1 = gr0 + 8;
            int s0 = __ldg(gsrc + gr0), d0 = __ldg(gdst + gr0);
            int s1 = __ldg(gsrc + gr1), d1 = __ldg(gdst + gr1);
#pragma unroll
            for (int nt = 0; nt < 4; nt++) {
                int gc = wn * 32 + nt * 8 + r4 * 2;
                float2 bv = *(const float2*)(bias + gc);
                float v0 = fmaxf(acc[mt][nt][0] + bv.x, 0.f);
                float v1 = fmaxf(acc[mt][nt][1] + bv.y, 0.f);
                float v2 = fmaxf(acc[mt][nt][2] + bv.x, 0.f);
                float v3 = fmaxf(acc[mt][nt][3] + bv.y, 0.f);
                redv2(&g_xout[(size_t)s0 * 128 + gc], v0, v1);
                redv2(&g_xin[(size_t)d0 * 128 + gc], v0, v1);
                redv2(&g_xout[(size_t)s1 * 128 + gc], v2, v3);
                redv2(&g_xin[(size_t)d1 * 128 + gc], v2, v3);
            }
        }
        // fused ea sums (fp32 exact re-read, L2 hot) + degree
        int row = tid >> 2, part = tid & 3;
        int e = rowBase + row;
        int s = __ldg(gsrc + e), d = __ldg(gdst + e);
        const float4* pea = (const float4*)(ea + (size_t)e * 64) + part * 4;
#pragma unroll
        for (int j = 0; j < 4; j++) {
            float4 v = pea[j];
            redv4(&g_lsum[(size_t)d * 64 + part * 16 + j * 4], v.x, v.y, v.z, v.w);
        }
        if (part == 0) { atomicAdd(&g_degs[s], 1.f); atomicAdd(&g_degd[d], 1.f); }
    }
}

// ======== fused c2 GEMM (K=128,N=64) + relu + c3 dot -> out[e] ========
__global__ __launch_bounds__(256)
void gemm_c2c3(const float* __restrict__ A, const float* __restrict__ B,
               const float* __restrict__ bias, const float* __restrict__ w3,
               const float* __restrict__ b3, float* __restrict__ out) {
    __shared__ unsigned As[128][36];
    __shared__ unsigned Bs[32][72];
    __shared__ float sp[128][2];
    int tid = threadIdx.x;
    int warp = tid >> 5, lane = tid & 31;
    int wm = warp & 3, wn = warp >> 2;   // 4 x 2
    int rowBase = blockIdx.x * 128;
    int q = lane >> 2, r4 = lane & 3;

    float acc[2][4][4];
#pragma unroll
    for (int mt = 0; mt < 2; mt++)
#pragma unroll
        for (int nt = 0; nt < 4; nt++)
#pragma unroll
            for (int j = 0; j < 4; j++) acc[mt][nt][j] = 0.f;

    for (int k0 = 0; k0 < 128; k0 += 32) {
#pragma unroll
        for (int i = 0; i < 4; i++) {
            int idx = tid + i * 256;
            int row = idx >> 3, kk = (idx & 7) * 4;
            float4 v = *(const float4*)(A + (size_t)(rowBase + row) * 128 + k0 + kk);
            uint4 t;
            t.x = f2tf(v.x); t.y = f2tf(v.y); t.z = f2tf(v.z); t.w = f2tf(v.w);
            *(uint4*)&As[row][kk] = t;
        }
#pragma unroll
        for (int i = 0; i < 2; i++) {
            int idx = tid + i * 256;
            int kk = idx >> 4, cc = (idx & 15) * 4;
            float4 v = *(const float4*)(B + (size_t)(k0 + kk) * 64 + cc);
            uint4 t;
            t.x = f2tf(v.x); t.y = f2tf(v.y); t.z = f2tf(v.z); t.w = f2tf(v.w);
            *(uint4*)&Bs[kk][cc] = t;
        }
        __syncthreads();
#pragma unroll
        for (int ks = 0; ks < 4; ks++) {
            int kb = ks * 8;
            unsigned af[2][4], bf[4][2];
#pragma unroll
            for (int mt = 0; mt < 2; mt++) {
                int r0 = wm * 32 + mt * 16 + q;
                af[mt][0] = As[r0][kb + r4];
                af[mt][1] = As[r0 + 8][kb + r4];
                af[mt][2] = As[r0][kb + r4 + 4];
                af[mt][3] = As[r0 + 8][kb + r4 + 4];
            }
#pragma unroll
            for (int nt = 0; nt < 4; nt++) {
                int c0 = wn * 32 + nt * 8 + q;
                bf[nt][0] = Bs[kb + r4][c0];
                bf[nt][1] = Bs[kb + r4 + 4][c0];
            }
#pragma unroll
            for (int mt = 0; mt < 2; mt++)
#pragma unroll
                for (int nt = 0; nt < 4; nt++) mma_tf32(acc[mt][nt], af[mt], bf[nt]);
        }
        __syncthreads();
    }

    // epilogue: relu(acc+bias) . w3, reduce across cols
    float p0[2] = {0.f, 0.f}, p1[2] = {0.f, 0.f};
#pragma unroll
    for (int mt = 0; mt < 2; mt++) {
#pragma unroll
        for (int nt = 0; nt < 4; nt++) {
            int gc = wn * 32 + nt * 8 + r4 * 2;
            float2 bv = *(const float2*)(bias + gc);
            float2 wv = *(const float2*)(w3 + gc);
            p0[mt] += fmaxf(acc[mt][nt][0] + bv.x, 0.f) * wv.x +
                      fmaxf(acc[mt][nt][1] + bv.y, 0.f) * wv.y;
            p1[mt] += fmaxf(acc[mt][nt][2] + bv.x, 0.f) * wv.x +
                      fmaxf(acc[mt][nt][3] + bv.y, 0.f) * wv.y;
        }
    }
#pragma unroll
    for (int mt = 0; mt < 2; mt++) {
        float a = p0[mt], b = p1[mt];
        a += __shfl_xor_sync(0xffffffffu, a, 1); a += __shfl_xor_sync(0xffffffffu, a, 2);
        b += __shfl_xor_sync(0xffffffffu, b, 1); b += __shfl_xor_sync(0xffffffffu, b, 2);
        if (r4 == 0) {
            sp[wm * 32 + mt * 16 + q][wn] = a;
            sp[wm * 32 + mt * 16 + 8 + q][wn] = b;
        }
    }
    __syncthreads();
    if (tid < 128) out[rowBase + tid] = sp[tid][0] + sp[tid][1] + b3[0];
}

// ---------------- fused ew GEMM + GATv2 logit ----------------
template <int H>
__global__ void k_logit_fused(const float* __restrict__ ea, const float* __restrict__ la,
                              const float* __restrict__ we, const float* __restrict__ att,
                              const float* __restrict__ xlr,
                              const int* __restrict__ src, const int* __restrict__ dst) {
    const int W = 2 * H * 128;
    const int XOFF = H * 128;
    const int NB = H * 128;
    __shared__ unsigned As[128][68];
    __shared__ unsigned Bs[32][72];
    __shared__ float sp[128][2];
    __shared__ float lg[H][128];
    int tid = threadIdx.x;
    int warp = tid >> 5, lane = tid & 31;
    int wm = warp & 3, wn = warp >> 2;
    int q = lane >> 2, r4 = lane & 3;
    int e0 = blockIdx.x * 128;

    for (int i = tid; i < H * 128; i += 256) lg[i >> 7][i & 127] = 0.f;

#pragma unroll
    for (int i = 0; i < 8; i++) {
        int idx = tid + i * 256;
        int row = idx >> 4, gc = (idx & 15) * 4;
        int e = e0 + row;
        float4 v = make_float4(0.f, 0.f, 0.f, 0.f);
        if (e < EE)      v = *(const float4*)(ea + (size_t)e * 64 + gc);
        else if (e < E2) v = *(const float4*)(la + (size_t)(e - EE) * 64 + gc);
        uint4 t;
        t.x = f2tf(v.x); t.y = f2tf(v.y); t.z = f2tf(v.z); t.w = f2tf(v.w);
        *(uint4*)&As[row][gc] = t;
    }
    int ss[2][2], dd[2][2];
    bool vld[2][2];
#pragma unroll
    for (int mt = 0; mt < 2; mt++)
#pragma unroll
        for (int hf = 0; hf < 2; hf++) {
            int e = e0 + wm * 32 + mt * 16 + hf * 8 + q;
            bool v = e < E2;
            vld[mt][hf] = v;
            if (!v) { ss[mt][hf] = 0; dd[mt][hf] = 0; }
            else if (e < EE) { ss[mt][hf] = __ldg(src + e); dd[mt][hf] = __ldg(dst + e); }
            else { ss[mt][hf] = e - EE; dd[mt][hf] = e - EE; }
        }
    __syncthreads();

    for (int strip = 0; strip < 2 * H; strip++) {
        float acc[2][4][4];
#pragma unroll
        for (int mt = 0; mt < 2; mt++)
#pragma unroll
            for (int nt = 0; nt < 4; nt++)
#pragma unroll
                for (int j = 0; j < 4; j++) acc[mt][nt][j] = 0.f;

        for (int kt = 0; kt < 2; kt++) {
            __syncthreads();
#pragma unroll
            for (int i = 0; i < 2; i++) {
                int idx = tid + i * 256;
                int kk = idx >> 4, cc = (idx & 15) * 4;
                float4 v = *(const float4*)(we + (size_t)(kt * 32 + kk) * NB + strip * 64 + cc);
                uint4 t;
                t.x = f2tf(v.x); t.y = f2tf(v.y); t.z = f2tf(v.z); t.w = f2tf(v.w);
                *(uint4*)&Bs[kk][cc] = t;
            }
            __syncthreads();
#pragma unroll
            for (int ks = 0; ks < 4; ks++) {
                int kb = ks * 8;
                unsigned af[2][4], bf[4][2];
#pragma unroll
                for (int mt = 0; mt < 2; mt++) {
                    int r0 = wm * 32 + mt * 16 + q;
                    int ka = kt * 32 + kb;
                    af[mt][0] = As[r0][ka + r4];
                    af[mt][1] = As[r0 + 8][ka + r4];
                    af[mt][2] = As[r0][ka + r4 + 4];
                    af[mt][3] = As[r0 + 8][ka + r4 + 4];
                }
#pragma unroll
                for (int nt = 0; nt < 4; nt++) {
                    int c0 = wn * 32 + nt * 8 + q;
                    bf[nt][0] = Bs[kb + r4][c0];
                    bf[nt][1] = Bs[kb + r4 + 4][c0];
                }
#pragma unroll
                for (int mt = 0; mt < 2; mt++)
#pragma unroll
                    for (int nt = 0; nt < 4; nt++) mma_tf32(acc[mt][nt], af[mt], bf[nt]);
            }
        }

        int h = strip >> 1;
        float prow[2][2] = {{0.f, 0.f}, {0.f, 0.f}};
#pragma unroll
        for (int mt = 0; mt < 2; mt++) {
#pragma unroll
            for (int nt = 0; nt < 4; nt++) {
                int gc = strip * 64 + wn * 32 + nt * 8 + r4 * 2;
                int ch = gc & 127;
                float2 at = *(const float2*)(att + h * 128 + ch);
                if (vld[mt][0]) {
                    float2 xv = *(const float2*)(xlr + (size_t)ss[mt][0] * W + h * 128 + ch);
                    float2 rv = *(const float2*)(xlr + (size_t)dd[mt][0] * W + XOFF + h * 128 + ch);
                    prow[mt][0] += lrelu02(acc[mt][nt][0] + xv.x + rv.x) * at.x +
                                   lrelu02(acc[mt][nt][1] + xv.y + rv.y) * at.y;
                }
                if (vld[mt][1]) {
                    float2 xv = *(const float2*)(xlr + (size_t)ss[mt][1] * W + h * 128 + ch);
                    float2 rv = *(const float2*)(xlr + (size_t)dd[mt][1] * W + XOFF + h * 128 + ch);
                    prow[mt][1] += lrelu02(acc[mt][nt][2] + xv.x + rv.x) * at.x +
                                   lrelu02(acc[mt][nt][3] + xv.y + rv.y) * at.y;
                }
            }
        }
#pragma unroll
        for (int mt = 0; mt < 2; mt++)
#pragma unroll
            for (int hf = 0; hf < 2; hf++) {
                float p = prow[mt][hf];
                p += __shfl_xor_sync(0xffffffffu, p, 1);
                p += __shfl_xor_sync(0xffffffffu, p, 2);
                if (r4 == 0) sp[wm * 32 + mt * 16 + hf * 8 + q][wn] = p;
            }
        __syncthreads();
        if (tid < 128) lg[h][tid] += sp[tid][0] + sp[tid][1];
    }
    __syncthreads();
    if (tid < 128) {
        int e = e0 + tid;
        if (e < E2) {
            int d = (e < EE) ? __ldg(dst + e) : (e - EE);
#pragma unroll
            for (int h = 0; h < H; h++) {
                float v = lg[h][tid];
                g_logit[(size_t)e * H + h] = v;
                atomicMaxFloat(&g_m[d * H + h], v);
            }
        }
    }
}

// ---------------- small kernels ----------------
__global__ void k_zero_stageA() {
    int i0 = blockIdx.x * blockDim.x + threadIdx.x;
    int stride = gridDim.x * blockDim.x;
    for (int t = i0; t < NN * 128; t += stride) { g_xout[t] = 0.f; g_xin[t] = 0.f; }
    for (int t = i0; t < NN * 64; t += stride) g_lsum[t] = 0.f;
    for (int t = i0; t < NN; t += stride) { g_degs[t] = 0.f; g_degd[t] = 0.f; }
}

__global__ void k_build_xi(const float* __restrict__ node_stats) {
    int i0 = blockIdx.x * blockDim.x + threadIdx.x;
    int stride = gridDim.x * blockDim.x;
    for (int t = i0; t < NN * 128; t += stride) {
        int v = t >> 7, c = t & 127;
        g_xi[(size_t)v * XI_LD + c] = g_xout[t] / fmaxf(g_degs[v], 1.f);
        g_xi[(size_t)v * XI_LD + 128 + c] = g_xin[t] / fmaxf(g_degd[v], 1.f);
    }
    for (int t = i0; t < NN * 64; t += stride) {
        int v = t >> 6;
        g_la[t] = g_lsum[t] / fmaxf(g_degd[v], 1.f);
    }
    for (int t = i0; t < NN * 8; t += stride) {
        int v = t >> 3, c = t & 7;
        g_xi[(size_t)v * XI_LD + 256 + c] = (c < 2) ? node_stats[v * 2 + c] : 0.f;
    }
}

__global__ void k_catw(const float* __restrict__ wl, const float* __restrict__ wr,
                       int K, int N1) {
    int i = blockIdx.x * blockDim.x + threadIdx.x;
    int tot = K * 2 * N1;
    if (i >= tot) return;
    int k = i / (2 * N1), j = i - k * 2 * N1;
    g_wcat[i] = (j < N1) ? wl[k * N1 + j] : wr[k * N1 + (j - N1)];
}

__global__ void k_zero_gat(int H) {
    int i0 = blockIdx.x * blockDim.x + threadIdx.x;
    int stride = gridDim.x * blockDim.x;
    for (int t = i0; t < NN * H * 128; t += stride) g_agg[t] = 0.f;
    for (int t = i0; t < NN * H; t += stride) { g_denom[t] = 0.f; g_m[t] = __int_as_float(0xff800000); }
}

// merged alpha + aggregation: unnormalized accumulate + denom
__global__ void k_gat_agg(const float* __restrict__ xlr, int W, const int* __restrict__ src,
                          const int* __restrict__ dst, int H) {
    int w = (blockIdx.x * blockDim.x + threadIdx.x) >> 5;
    int lane = threadIdx.x & 31;
    if (w >= E2) return;
    int s, d;
    if (w < EE) { s = src[w]; d = dst[w]; }
    else { s = d = w - EE; }
    for (int h = 0; h < H; h++) {
        float a = expf(g_logit[(size_t)w * H + h] - g_m[d * H + h]);
        if (lane == 0) atomicAdd(&g_denom[d * H + h], a);
        float4 x = ((const float4*)(xlr + (size_t)s * W + h * 128))[lane];
        redv4(&g_agg[((size_t)d * H + h) * 128 + lane * 4],
              a * x.x, a * x.y, a * x.z, a * x.w);
    }
}

__global__ void k_gat_final(const float* __restrict__ bias, const float* __restrict__ gam,
                            const float* __restrict__ bet, float* __restrict__ out, int H) {
    int v = (blockIdx.x * blockDim.x + threadIdx.x) >> 5;
    int lane = threadIdx.x & 31;
    if (v >= NN) return;
    float vals[4];
    int c0 = lane * 4;
    if (H == 2) {
        float i0 = 1.f / fmaxf(g_denom[v * 2 + 0], 1e-16f);
        float i1 = 1.f / fmaxf(g_denom[v * 2 + 1], 1e-16f);
        float4 a = ((const float4*)(g_agg + (size_t)v * 256))[lane];
        float4 b = ((const float4*)(g_agg + (size_t)v * 256 + 128))[lane];
        vals[0] = 0.5f * (a.x * i0 + b.x * i1) + bias[c0 + 0];
        vals[1] = 0.5f * (a.y * i0 + b.y * i1) + bias[c0 + 1];
        vals[2] = 0.5f * (a.z * i0 + b.z * i1) + bias[c0 + 2];
        vals[3] = 0.5f * (a.w * i0 + b.w * i1) + bias[c0 + 3];
    } else {
        float i0 = 1.f / fmaxf(g_denom[v], 1e-16f);
        float4 a = ((const float4*)(g_agg + (size_t)v * 128))[lane];
        vals[0] = a.x * i0 + bias[c0 + 0];
        vals[1] = a.y * i0 + bias[c0 + 1];
        vals[2] = a.z * i0 + bias[c0 + 2];
        vals[3] = a.w * i0 + bias[c0 + 3];
    }
    float mu = warp_sum(vals[0] + vals[1] + vals[2] + vals[3]) * (1.f / 128.f);
    float sq = 0.f;
#pragma unroll
    for (int j = 0; j < 4; j++) { float dlt = vals[j] - mu; sq += dlt * dlt; }
    float var = warp_sum(sq) * (1.f / 128.f);
    float rstd = rsqrtf(var + 1e-5f);
#pragma unroll
    for (int j = 0; j < 4; j++) {
        int c = c0 + j;
        float y = (vals[j] - mu) * rstd * gam[c] + bet[c];
        out[(size_t)v * 128 + c] = y > 0.f ? y : (expf(y) - 1.f);
    }
}

// ---------------- host ----------------
static float* sym(const void* s) { void* p = nullptr; cudaGetSymbolAddress(&p, s); return (float*)p; }

extern "C" void kernel_launch(void* const* d_in, const int* in_sizes, int n_in,
                              void* d_out, int out_size) {
    const float* node_stats = (const float*)d_in[1];
    const int*   edge_index = (const int*)d_in[2];
    const float* edge_attr  = (const float*)d_in[3];
    const float* epw = (const float*)d_in[4];
    const float* epb = (const float*)d_in[5];
    const float* g1wl = (const float*)d_in[6];
    const float* g1wr = (const float*)d_in[7];
    const float* g1we = (const float*)d_in[8];
    const float* g1att = (const float*)d_in[9];
    const float* g1b = (const float*)d_in[10];
    const float* n1g = (const float*)d_in[11];
    const float* n1b = (const float*)d_in[12];
    const float* g2wl = (const float*)d_in[13];
    const float* g2wr = (const float*)d_in[14];
    const float* g2we = (const float*)d_in[15];
    const float* g2att = (const float*)d_in[16];
    const float* g2b = (const float*)d_in[17];
    const float* n2g = (const float*)d_in[18];
    const float* n2b = (const float*)d_in[19];
    const float* c1w = (const float*)d_in[20];
    const float* c1b = (const float*)d_in[21];
    const float* c2w = (const float*)d_in[22];
    const float* c2b = (const float*)d_in[23];
    const float* c3w = (const float*)d_in[24];
    const float* c3b = (const float*)d_in[25];

    const int* src = edge_index;
    const int* dst = edge_index + EE;

    float* p_cls1 = sym(g_cls1);
    float* p_xi   = sym(g_xi);
    float* p_xlr  = sym(g_xlr);
    float* p_la   = sym(g_la);
    float* p_h1   = sym(g_h1);
    float* p_h2   = sym(g_h2);
    float* p_wcat = sym(g_wcat);

    const int T = 256;
    dim3 gE2warp((E2 + 7) / 8);
    dim3 gNwarp((NN + 7) / 8);
    const int MB_E = EE / 128;                 // 3125
    const int MB_N = (NN + 127) / 128;         // 391
    const int NB_L = (E2 + 127) / 128;         // 3516

    // ---- Stage A: fused edge-MLP + scatter + ea sums, then xi ----
    k_zero_stageA<<<1024, T>>>();
    gemm128<1, 0, 1><<<dim3(1, MB_E), 512>>>(edge_attr, 64, 64, epw, epb, nullptr, EE, 128,
                                             src, dst, nullptr, edge_attr);
    k_build_xi<<<1024, T>>>(node_stats);

    // ---- GAT layer 1 (H=2) ----
    k_catw<<<(258 * 512 + T - 1) / T, T>>>(g1wl, g1wr, 258, 256);
    gemm128<0, 0, 0><<<dim3(4, MB_N), 512>>>(p_xi, XI_LD, 258, p_wcat, nullptr, p_xlr, NN, 512,
                                             nullptr, nullptr, nullptr, nullptr);
    k_zero_gat<<<1024, T>>>(2);
    k_logit_fused<2><<<NB_L, T>>>(edge_attr, p_la, g1we, g1att, p_xlr, src, dst);
    k_gat_agg<<<gE2warp, T>>>(p_xlr, 512, src, dst, 2);
    k_gat_final<<<gNwarp, T>>>(g1b, n1g, n1b, p_h1, 2);

    // ---- GAT layer 2 (H=1) ----
    k_catw<<<(128 * 256 + T - 1) / T, T>>>(g2wl, g2wr, 128, 128);
    gemm128<0, 0, 0><<<dim3(2, MB_N), 512>>>(p_h1, 128, 128, p_wcat, nullptr, p_xlr, NN, 256,
                                             nullptr, nullptr, nullptr, nullptr);
    k_zero_gat<<<1024, T>>>(1);
    k_logit_fused<1><<<NB_L, T>>>(edge_attr, p_la, g2we, g2att, p_xlr, src, dst);
    k_gat_agg<<<gE2warp, T>>>(p_xlr, 256, src, dst, 1);
    k_gat_final<<<gNwarp, T>>>(g2b, n2g, n2b, p_h2, 1);

    // ---- Classifier: c1 (fused gather), then fused c2+c3 ----
    gemm128<1, 1, 0><<<dim3(1, MB_E), 512>>>(nullptr, 320, 320, c1w, c1b, p_cls1, EE, 128,
                                             src, dst, p_h2, edge_attr);
    gemm_c2c3<<<MB_E, T>>>(p_cls1, c2w, c2b, c3w, c3b, (float*)d_out);
}

// round 5
// speedup vs baseline: 3.5520x; 1.0616x over previous
#include <cuda_runtime.h>
#include <math.h>

#define NN 50000
#define EE 400000
#define E2 (EE + 50000)
#define XI_LD 264   // padded leading dim for xi (K=258)

// ---------------- scratch ----------------
__device__ float g_xi[NN * XI_LD + 64];
__device__ float g_xlr[NN * 512 + 64];   // [node][xl(H*128) | xr(H*128)]
__device__ float g_la[NN * 64 + 64];
__device__ float g_xout[NN * 128];
__device__ float g_xin[NN * 128];
__device__ float g_lsum[NN * 64];
__device__ float g_degs[NN];
__device__ float g_degd[NN];
__device__ float g_agg1[NN * 256];
__device__ float g_agg2[NN * 128];
__device__ float g_h1[NN * 128 + 64];
__device__ float g_h2[NN * 128 + 64];
__device__ float g_den1[NN * 2];
__device__ float g_den2[NN];
__device__ float g_wcat[264 * 512];

// ---------------- helpers ----------------
__device__ __forceinline__ float lrelu02(float x) { return x > 0.f ? x : 0.2f * x; }

__device__ __forceinline__ float warp_sum(float v) {
#pragma unroll
    for (int o = 16; o; o >>= 1) v += __shfl_xor_sync(0xffffffffu, v, o);
    return v;
}

__device__ __forceinline__ void redv2(float* p, float a, float b) {
    asm volatile("red.global.add.v2.f32 [%0], {%1, %2};" :: "l"(p), "f"(a), "f"(b) : "memory");
}
__device__ __forceinline__ void redv4(float* p, float a, float b, float c, float d) {
    asm volatile("red.global.add.v4.f32 [%0], {%1, %2, %3, %4};"
                 :: "l"(p), "f"(a), "f"(b), "f"(c), "f"(d) : "memory");
}

__device__ __forceinline__ unsigned f2tf(float x) {
    unsigned u;
    asm("cvt.rna.tf32.f32 %0, %1;" : "=r"(u) : "f"(x));
    return u;
}

__device__ __forceinline__ void mma_tf32(float c[4], const unsigned a[4], const unsigned b[2]) {
    asm volatile(
        "mma.sync.aligned.m16n8k8.row.col.f32.tf32.tf32.f32 "
        "{%0,%1,%2,%3},{%4,%5,%6,%7},{%8,%9},{%0,%1,%2,%3};"
        : "+f"(c[0]), "+f"(c[1]), "+f"(c[2]), "+f"(c[3])
        : "r"(a[0]), "r"(a[1]), "r"(a[2]), "r"(a[3]), "r"(b[0]), "r"(b[1]));
}

// ======== wide TF32 GEMM: BM=128 BN=128 BK=32, 512 threads (16 warps 4x4) ========
// EPI: 0 = store C (+relu if ACT), 1 = emb scatter + ea sums (no C store)
template <int ACT, int GATHER, int EPI>
__global__ __launch_bounds__(512, 1)
void gemm128(const float* __restrict__ A, int lda, int K,
             const float* __restrict__ B,
             const float* __restrict__ bias,
             float* __restrict__ C, int M, int N,
             const int* __restrict__ gsrc, const int* __restrict__ gdst,
             const float* __restrict__ h2, const float* __restrict__ ea) {
    __shared__ unsigned As[128][36];
    __shared__ unsigned Bs[32][136];
    int tid = threadIdx.x;
    int warp = tid >> 5, lane = tid & 31;
    int wm = warp & 3, wn = warp >> 2;
    int rowBase = blockIdx.y * 128;
    int colBase = blockIdx.x * 128;
    int q = lane >> 2, r4 = lane & 3;

    float acc[2][4][4];
#pragma unroll
    for (int mt = 0; mt < 2; mt++)
#pragma unroll
        for (int nt = 0; nt < 4; nt++)
#pragma unroll
            for (int j = 0; j < 4; j++) acc[mt][nt][j] = 0.f;

    float4 pa[2], pb[2];

    auto loadA = [&](int k0) {
#pragma unroll
        for (int i = 0; i < 2; i++) {
            int idx = tid + i * 512;
            int row = idx >> 3, kk = (idx & 7) * 4;
            int gk = k0 + kk;
            float4 v = make_float4(0.f, 0.f, 0.f, 0.f);
            if (GATHER) {
                int e = rowBase + row;
                const float* p;
                if (k0 < 128)      p = h2 + (size_t)gsrc[e] * 128 + gk;
                else if (k0 < 256) p = h2 + (size_t)gdst[e] * 128 + (gk - 128);
                else               p = ea + (size_t)e * 64 + (gk - 256);
                v = *(const float4*)p;
            } else {
                int gr = rowBase + row;
                if (gr < M && gk < lda) v = *(const float4*)(A + (size_t)gr * lda + gk);
            }
            pa[i] = v;
        }
    };
    auto loadB = [&](int k0) {
#pragma unroll
        for (int i = 0; i < 2; i++) {
            int idx = tid + i * 512;
            int kk = idx >> 5, cc = (idx & 31) * 4;
            int gk = k0 + kk;
            float4 v = make_float4(0.f, 0.f, 0.f, 0.f);
            if (gk < K) v = *(const float4*)(B + (size_t)gk * N + colBase + cc);
            pb[i] = v;
        }
    };
    auto stsAB = [&]() {
#pragma unroll
        for (int i = 0; i < 2; i++) {
            int idx = tid + i * 512;
            int row = idx >> 3, kk = (idx & 7) * 4;
            uint4 t;
            t.x = f2tf(pa[i].x); t.y = f2tf(pa[i].y); t.z = f2tf(pa[i].z); t.w = f2tf(pa[i].w);
            *(uint4*)&As[row][kk] = t;
            int kb = idx >> 5, cc = (idx & 31) * 4;
            uint4 u;
            u.x = f2tf(pb[i].x); u.y = f2tf(pb[i].y); u.z = f2tf(pb[i].z); u.w = f2tf(pb[i].w);
            *(uint4*)&Bs[kb][cc] = u;
        }
    };

    loadA(0); loadB(0);
    for (int k0 = 0; k0 < K; k0 += 32) {
        stsAB();
        __syncthreads();
        if (k0 + 32 < K) { loadA(k0 + 32); loadB(k0 + 32); }
#pragma unroll
        for (int ks = 0; ks < 4; ks++) {
            int kb = ks * 8;
            unsigned af[2][4], bf[4][2];
#pragma unroll
            for (int mt = 0; mt < 2; mt++) {
                int r0 = wm * 32 + mt * 16 + q;
                af[mt][0] = As[r0][kb + r4];
                af[mt][1] = As[r0 + 8][kb + r4];
                af[mt][2] = As[r0][kb + r4 + 4];
                af[mt][3] = As[r0 + 8][kb + r4 + 4];
            }
#pragma unroll
            for (int nt = 0; nt < 4; nt++) {
                int c0 = wn * 32 + nt * 8 + q;
                bf[nt][0] = Bs[kb + r4][c0];
                bf[nt][1] = Bs[kb + r4 + 4][c0];
            }
#pragma unroll
            for (int mt = 0; mt < 2; mt++)
#pragma unroll
                for (int nt = 0; nt < 4; nt++) mma_tf32(acc[mt][nt], af[mt], bf[nt]);
        }
        __syncthreads();
    }

    if (EPI == 0) {
#pragma unroll
        for (int mt = 0; mt < 2; mt++) {
            int gr0 = rowBase + wm * 32 + mt * 16 + q;
            int gr1 = gr0 + 8;
#pragma unroll
            for (int nt = 0; nt < 4; nt++) {
                int gc = colBase + wn * 32 + nt * 8 + r4 * 2;
                float2 bv = make_float2(0.f, 0.f);
                if (bias) bv = *(const float2*)(bias + gc);
                float o0 = acc[mt][nt][0] + bv.x, o1 = acc[mt][nt][1] + bv.y;
                float o2 = acc[mt][nt][2] + bv.x, o3 = acc[mt][nt][3] + bv.y;
                if (ACT == 1) {
                    o0 = fmaxf(o0, 0.f); o1 = fmaxf(o1, 0.f);
                    o2 = fmaxf(o2, 0.f); o3 = fmaxf(o3, 0.f);
                }
                if (gr0 < M) *(float2*)(C + (size_t)gr0 * N + gc) = make_float2(o0, o1);
                if (gr1 < M) *(float2*)(C + (size_t)gr1 * N + gc) = make_float2(o2, o3);
            }
        }
    } else {
        // emb scatter: relu(acc+bias) -> xout[src], xin[dst]
#pragma unroll
        for (int mt = 0; mt < 2; mt++) {
            int gr0 = rowBase + wm * 32 + mt * 16 + q;
            int gr1 = gr0 + 8;
            int s0 = __ldg(gsrc + gr0), d0 = __ldg(gdst + gr0);
            int s1 = __ldg(gsrc + gr1), d1 = __ldg(gdst + gr1);
#pragma unroll
            for (int nt = 0; nt < 4; nt++) {
                int gc = wn * 32 + nt * 8 + r4 * 2;
                float2 bv = *(const float2*)(bias + gc);
                float v0 = fmaxf(acc[mt][nt][0] + bv.x, 0.f);
                float v1 = fmaxf(acc[mt][nt][1] + bv.y, 0.f);
                float v2 = fmaxf(acc[mt][nt][2] + bv.x, 0.f);
                float v3 = fmaxf(acc[mt][nt][3] + bv.y, 0.f);
                redv2(&g_xout[(size_t)s0 * 128 + gc], v0, v1);
                redv2(&g_xin[(size_t)d0 * 128 + gc], v0, v1);
                redv2(&g_xout[(size_t)s1 * 128 + gc], v2, v3);
                redv2(&g_xin[(size_t)d1 * 128 + gc], v2, v3);
            }
        }
        // fused ea sums + degree
        int row = tid >> 2, part = tid & 3;
        int e = rowBase + row;
        int s = __ldg(gsrc + e), d = __ldg(gdst + e);
        const float4* pea = (const float4*)(ea + (size_t)e * 64) + part * 4;
#pragma unroll
        for (int j = 0; j < 4; j++) {
            float4 v = pea[j];
            redv4(&g_lsum[(size_t)d * 64 + part * 16 + j * 4], v.x, v.y, v.z, v.w);
        }
        if (part == 0) { atomicAdd(&g_degs[s], 1.f); atomicAdd(&g_degd[d], 1.f); }
    }
}

// ======== fully fused classifier: gather-c1 GEMM -> relu -> c2 GEMM -> relu -> c3 dot ========
__global__ __launch_bounds__(512, 1)
void gemm_c1c2c3(const float* __restrict__ c1w, const float* __restrict__ c1b,
                 const float* __restrict__ c2w, const float* __restrict__ c2b,
                 const float* __restrict__ w3, const float* __restrict__ b3,
                 const int* __restrict__ gsrc, const int* __restrict__ gdst,
                 const float* __restrict__ h2, const float* __restrict__ ea,
                 float* __restrict__ out) {
    __shared__ unsigned As[128][36];
    __shared__ unsigned Bs[32][136];
    __shared__ float sp[128][4];
    int tid = threadIdx.x;
    int warp = tid >> 5, lane = tid & 31;
    int wm = warp & 3, wn = warp >> 2;
    int rowBase = blockIdx.x * 128;
    int q = lane >> 2, r4 = lane & 3;

    // ---- stage 1: c1 = relu(gather(A) @ c1w + c1b), K=320, N=128 ----
    float acc[2][4][4];
#pragma unroll
    for (int mt = 0; mt < 2; mt++)
#pragma unroll
        for (int nt = 0; nt < 4; nt++)
#pragma unroll
            for (int j = 0; j < 4; j++) acc[mt][nt][j] = 0.f;

    float4 pa[2], pb[2];
    auto loadA = [&](int k0) {
#pragma unroll
        for (int i = 0; i < 2; i++) {
            int idx = tid + i * 512;
            int row = idx >> 3, kk = (idx & 7) * 4;
            int gk = k0 + kk;
            int e = rowBase + row;
            const float* p;
            if (k0 < 128)      p = h2 + (size_t)__ldg(gsrc + e) * 128 + gk;
            else if (k0 < 256) p = h2 + (size_t)__ldg(gdst + e) * 128 + (gk - 128);
            else               p = ea + (size_t)e * 64 + (gk - 256);
            pa[i] = *(const float4*)p;
        }
    };
    auto loadB = [&](int k0) {
#pragma unroll
        for (int i = 0; i < 2; i++) {
            int idx = tid + i * 512;
            int kk = idx >> 5, cc = (idx & 31) * 4;
            pb[i] = *(const float4*)(c1w + (size_t)(k0 + kk) * 128 + cc);
        }
    };
    auto stsAB = [&]() {
#pragma unroll
        for (int i = 0; i < 2; i++) {
            int idx = tid + i * 512;
            int row = idx >> 3, kk = (idx & 7) * 4;
            uint4 t;
            t.x = f2tf(pa[i].x); t.y = f2tf(pa[i].y); t.z = f2tf(pa[i].z); t.w = f2tf(pa[i].w);
            *(uint4*)&As[row][kk] = t;
            int kb = idx >> 5, cc = (idx & 31) * 4;
            uint4 u;
            u.x = f2tf(pb[i].x); u.y = f2tf(pb[i].y); u.z = f2tf(pb[i].z); u.w = f2tf(pb[i].w);
            *(uint4*)&Bs[kb][cc] = u;
        }
    };

    loadA(0); loadB(0);
    for (int k0 = 0; k0 < 320; k0 += 32) {
        stsAB();
        __syncthreads();
        if (k0 + 32 < 320) { loadA(k0 + 32); loadB(k0 + 32); }
#pragma unroll
        for (int ks = 0; ks < 4; ks++) {
            int kb = ks * 8;
            unsigned af[2][4], bf[4][2];
#pragma unroll
            for (int mt = 0; mt < 2; mt++) {
                int r0 = wm * 32 + mt * 16 + q;
                af[mt][0] = As[r0][kb + r4];
                af[mt][1] = As[r0 + 8][kb + r4];
                af[mt][2] = As[r0][kb + r4 + 4];
                af[mt][3] = As[r0 + 8][kb + r4 + 4];
            }
#pragma unroll
            for (int nt = 0; nt < 4; nt++) {
                int c0 = wn * 32 + nt * 8 + q;
                bf[nt][0] = Bs[kb + r4][c0];
                bf[nt][1] = Bs[kb + r4 + 4][c0];
            }
#pragma unroll
            for (int mt = 0; mt < 2; mt++)
#pragma unroll
                for (int nt = 0; nt < 4; nt++) mma_tf32(acc[mt][nt], af[mt], bf[nt]);
        }
        __syncthreads();
    }

    // ---- stage 2: c2 accum over 4 K-chunks of the in-register c1 tile ----
    float acc2[2][2][4];
#pragma unroll
    for (int mt = 0; mt < 2; mt++)
#pragma unroll
        for (int nt = 0; nt < 2; nt++)
#pragma unroll
            for (int j = 0; j < 4; j++) acc2[mt][nt][j] = 0.f;

    for (int kc = 0; kc < 4; kc++) {
        __syncthreads();
        if (wn == kc) {
#pragma unroll
            for (int mt = 0; mt < 2; mt++) {
                int r0 = wm * 32 + mt * 16 + q, r1 = r0 + 8;
#pragma unroll
                for (int nt = 0; nt < 4; nt++) {
                    int lc = nt * 8 + r4 * 2;
                    int gc = kc * 32 + lc;
                    float2 bv = *(const float2*)(c1b + gc);
                    As[r0][lc]     = f2tf(fmaxf(acc[mt][nt][0] + bv.x, 0.f));
                    As[r0][lc + 1] = f2tf(fmaxf(acc[mt][nt][1] + bv.y, 0.f));
                    As[r1][lc]     = f2tf(fmaxf(acc[mt][nt][2] + bv.x, 0.f));
                    As[r1][lc + 1] = f2tf(fmaxf(acc[mt][nt][3] + bv.y, 0.f));
                }
            }
        }
        // load c2w chunk [32 x 64]
        {
            int kk = tid >> 4, cc = (tid & 15) * 4;
            float4 v = *(const float4*)(c2w + (size_t)(kc * 32 + kk) * 64 + cc);
            uint4 t;
            t.x = f2tf(v.x); t.y = f2tf(v.y); t.z = f2tf(v.z); t.w = f2tf(v.w);
            *(uint4*)&Bs[kk][cc] = t;
        }
        __syncthreads();
#pragma unroll
        for (int ks = 0; ks < 4; ks++) {
            int kb = ks * 8;
            unsigned af[2][4], bf[2][2];
#pragma unroll
            for (int mt = 0; mt < 2; mt++) {
                int r0 = wm * 32 + mt * 16 + q;
                af[mt][0] = As[r0][kb + r4];
                af[mt][1] = As[r0 + 8][kb + r4];
                af[mt][2] = As[r0][kb + r4 + 4];
                af[mt][3] = As[r0 + 8][kb + r4 + 4];
            }
#pragma unroll
            for (int nt = 0; nt < 2; nt++) {
                int c0 = wn * 16 + nt * 8 + q;
                bf[nt][0] = Bs[kb + r4][c0];
                bf[nt][1] = Bs[kb + r4 + 4][c0];
            }
#pragma unroll
            for (int mt = 0; mt < 2; mt++)
#pragma unroll
                for (int nt = 0; nt < 2; nt++) mma_tf32(acc2[mt][nt], af[mt], bf[nt]);
        }
    }

    // ---- stage 3: relu(c2) . w3 + b3 -> out ----
    float p0[2] = {0.f, 0.f}, p1[2] = {0.f, 0.f};
#pragma unroll
    for (int mt = 0; mt < 2; mt++) {
#pragma unroll
        for (int nt = 0; nt < 2; nt++) {
            int gc = wn * 16 + nt * 8 + r4 * 2;
            float2 bv = *(const float2*)(c2b + gc);
            float2 wv = *(const float2*)(w3 + gc);
            p0[mt] += fmaxf(acc2[mt][nt][0] + bv.x, 0.f) * wv.x +
                      fmaxf(acc2[mt][nt][1] + bv.y, 0.f) * wv.y;
            p1[mt] += fmaxf(acc2[mt][nt][2] + bv.x, 0.f) * wv.x +
                      fmaxf(acc2[mt][nt][3] + bv.y, 0.f) * wv.y;
        }
    }
    __syncthreads();
#pragma unroll
    for (int mt = 0; mt < 2; mt++) {
        float a = p0[mt], b = p1[mt];
        a += __shfl_xor_sync(0xffffffffu, a, 1); a += __shfl_xor_sync(0xffffffffu, a, 2);
        b += __shfl_xor_sync(0xffffffffu, b, 1); b += __shfl_xor_sync(0xffffffffu, b, 2);
        if (r4 == 0) {
            sp[wm * 32 + mt * 16 + q][wn] = a;
            sp[wm * 32 + mt * 16 + 8 + q][wn] = b;
        }
    }
    __syncthreads();
    if (tid < 128)
        out[rowBase + tid] = sp[tid][0] + sp[tid][1] + sp[tid][2] + sp[tid][3] + b3[0];
}

// ======== merged: ew GEMM + GATv2 logit + exp + aggregation ========
template <int H>
__global__ void k_gat_edge(const float* __restrict__ ea, const float* __restrict__ la,
                           const float* __restrict__ we, const float* __restrict__ att,
                           const float* __restrict__ xlr,
                           const int* __restrict__ src, const int* __restrict__ dst,
                           float* __restrict__ agg, float* __restrict__ denom) {
    const int W = 2 * H * 128;
    const int XOFF = H * 128;
    const int NB = H * 128;
    __shared__ unsigned As[128][68];
    __shared__ unsigned Bs[32][72];
    __shared__ float sp[128][2];
    __shared__ float lg[H][128];
    int tid = threadIdx.x;
    int warp = tid >> 5, lane = tid & 31;
    int wm = warp & 3, wn = warp >> 2;
    int q = lane >> 2, r4 = lane & 3;
    int e0 = blockIdx.x * 128;

    for (int i = tid; i < H * 128; i += 256) lg[i >> 7][i & 127] = 0.f;

#pragma unroll
    for (int i = 0; i < 8; i++) {
        int idx = tid + i * 256;
        int row = idx >> 4, gc = (idx & 15) * 4;
        int e = e0 + row;
        float4 v = make_float4(0.f, 0.f, 0.f, 0.f);
        if (e < EE)      v = *(const float4*)(ea + (size_t)e * 64 + gc);
        else if (e < E2) v = *(const float4*)(la + (size_t)(e - EE) * 64 + gc);
        uint4 t;
        t.x = f2tf(v.x); t.y = f2tf(v.y); t.z = f2tf(v.z); t.w = f2tf(v.w);
        *(uint4*)&As[row][gc] = t;
    }
    int ss[2][2], dd[2][2];
    bool vld[2][2];
#pragma unroll
    for (int mt = 0; mt < 2; mt++)
#pragma unroll
        for (int hf = 0; hf < 2; hf++) {
            int e = e0 + wm * 32 + mt * 16 + hf * 8 + q;
            bool v = e < E2;
            vld[mt][hf] = v;
            if (!v) { ss[mt][hf] = 0; dd[mt][hf] = 0; }
            else if (e < EE) { ss[mt][hf] = __ldg(src + e); dd[mt][hf] = __ldg(dst + e); }
            else { ss[mt][hf] = e - EE; dd[mt][hf] = e - EE; }
        }
    __syncthreads();

    for (int strip = 0; strip < 2 * H; strip++) {
        float acc[2][4][4];
#pragma unroll
        for (int mt = 0; mt < 2; mt++)
#pragma unroll
            for (int nt = 0; nt < 4; nt++)
#pragma unroll
                for (int j = 0; j < 4; j++) acc[mt][nt][j] = 0.f;

        for (int kt = 0; kt < 2; kt++) {
            __syncthreads();
#pragma unroll
            for (int i = 0; i < 2; i++) {
                int idx = tid + i * 256;
                int kk = idx >> 4, cc = (idx & 15) * 4;
                float4 v = *(const float4*)(we + (size_t)(kt * 32 + kk) * NB + strip * 64 + cc);
                uint4 t;
                t.x = f2tf(v.x); t.y = f2tf(v.y); t.z = f2tf(v.z); t.w = f2tf(v.w);
                *(uint4*)&Bs[kk][cc] = t;
            }
            __syncthreads();
#pragma unroll
            for (int ks = 0; ks < 4; ks++) {
                int kb = ks * 8;
                unsigned af[2][4], bf[4][2];
#pragma unroll
                for (int mt = 0; mt < 2; mt++) {
                    int r0 = wm * 32 + mt * 16 + q;
                    int ka = kt * 32 + kb;
                    af[mt][0] = As[r0][ka + r4];
                    af[mt][1] = As[r0 + 8][ka + r4];
                    af[mt][2] = As[r0][ka + r4 + 4];
                    af[mt][3] = As[r0 + 8][ka + r4 + 4];
                }
#pragma unroll
                for (int nt = 0; nt < 4; nt++) {
                    int c0 = wn * 32 + nt * 8 + q;
                    bf[nt][0] = Bs[kb + r4][c0];
                    bf[nt][1] = Bs[kb + r4 + 4][c0];
                }
#pragma unroll
                for (int mt = 0; mt < 2; mt++)
#pragma unroll
                    for (int nt = 0; nt < 4; nt++) mma_tf32(acc[mt][nt], af[mt], bf[nt]);
            }
        }

        int h = strip >> 1;
        float prow[2][2] = {{0.f, 0.f}, {0.f, 0.f}};
#pragma unroll
        for (int mt = 0; mt < 2; mt++) {
#pragma unroll
            for (int nt = 0; nt < 4; nt++) {
                int gc = strip * 64 + wn * 32 + nt * 8 + r4 * 2;
                int ch = gc & 127;
                float2 at = *(const float2*)(att + h * 128 + ch);
                if (vld[mt][0]) {
                    float2 xv = *(const float2*)(xlr + (size_t)ss[mt][0] * W + h * 128 + ch);
                    float2 rv = *(const float2*)(xlr + (size_t)dd[mt][0] * W + XOFF + h * 128 + ch);
                    prow[mt][0] += lrelu02(acc[mt][nt][0] + xv.x + rv.x) * at.x +
                                   lrelu02(acc[mt][nt][1] + xv.y + rv.y) * at.y;
                }
                if (vld[mt][1]) {
                    float2 xv = *(const float2*)(xlr + (size_t)ss[mt][1] * W + h * 128 + ch);
                    float2 rv = *(const float2*)(xlr + (size_t)dd[mt][1] * W + XOFF + h * 128 + ch);
                    prow[mt][1] += lrelu02(acc[mt][nt][2] + xv.x + rv.x) * at.x +
                                   lrelu02(acc[mt][nt][3] + xv.y + rv.y) * at.y;
                }
            }
        }
#pragma unroll
        for (int mt = 0; mt < 2; mt++)
#pragma unroll
            for (int hf = 0; hf < 2; hf++) {
                float p = prow[mt][hf];
                p += __shfl_xor_sync(0xffffffffu, p, 1);
                p += __shfl_xor_sync(0xffffffffu, p, 2);
                if (r4 == 0) sp[wm * 32 + mt * 16 + hf * 8 + q][wn] = p;
            }
        __syncthreads();
        if (tid < 128) lg[h][tid] += sp[tid][0] + sp[tid][1];
    }
    __syncthreads();

    // aggregation: a = exp(logit) (no max needed; logits O(1)); warp per edge
    for (int e_loc = warp; e_loc < 128; e_loc += 8) {
        int e = e0 + e_loc;
        if (e >= E2) break;
        int s, d;
        if (e < EE) { s = __ldg(src + e); d = __ldg(dst + e); }
        else { s = d = e - EE; }
#pragma unroll
        for (int h = 0; h < H; h++) {
            float a = expf(lg[h][e_loc]);
            if (lane == 0) atomicAdd(&denom[d * H + h], a);
            float4 v = ((const float4*)(xlr + (size_t)s * W + h * 128))[lane];
            redv4(&agg[((size_t)d * H + h) * 128 + lane * 4],
                  a * v.x, a * v.y, a * v.z, a * v.w);
        }
    }
}

// ---------------- small kernels ----------------
__global__ void k_zero_all() {
    int i0 = blockIdx.x * blockDim.x + threadIdx.x;
    int stride = gridDim.x * blockDim.x;
    for (int t = i0; t < NN * 128; t += stride) { g_xout[t] = 0.f; g_xin[t] = 0.f; g_agg2[t] = 0.f; }
    for (int t = i0; t < NN * 256; t += stride) g_agg1[t] = 0.f;
    for (int t = i0; t < NN * 64; t += stride) g_lsum[t] = 0.f;
    for (int t = i0; t < NN; t += stride) {
        g_degs[t] = 0.f; g_degd[t] = 0.f;
        g_den1[t * 2] = 0.f; g_den1[t * 2 + 1] = 0.f; g_den2[t] = 0.f;
    }
}

__global__ void k_build_xi(const float* __restrict__ node_stats) {
    int i0 = blockIdx.x * blockDim.x + threadIdx.x;
    int stride = gridDim.x * blockDim.x;
    for (int t = i0; t < NN * 128; t += stride) {
        int v = t >> 7, c = t & 127;
        g_xi[(size_t)v * XI_LD + c] = g_xout[t] / fmaxf(g_degs[v], 1.f);
        g_xi[(size_t)v * XI_LD + 128 + c] = g_xin[t] / fmaxf(g_degd[v], 1.f);
    }
    for (int t = i0; t < NN * 64; t += stride) {
        int v = t >> 6;
        g_la[t] = g_lsum[t] / fmaxf(g_degd[v], 1.f);
    }
    for (int t = i0; t < NN * 8; t += stride) {
        int v = t >> 3, c = t & 7;
        g_xi[(size_t)v * XI_LD + 256 + c] = (c < 2) ? node_stats[v * 2 + c] : 0.f;
    }
}

__global__ void k_catw(const float* __restrict__ wl, const float* __restrict__ wr,
                       int K, int N1) {
    int i = blockIdx.x * blockDim.x + threadIdx.x;
    int tot = K * 2 * N1;
    if (i >= tot) return;
    int k = i / (2 * N1), j = i - k * 2 * N1;
    g_wcat[i] = (j < N1) ? wl[k * N1 + j] : wr[k * N1 + (j - N1)];
}

__global__ void k_gat_final(const float* __restrict__ bias, const float* __restrict__ gam,
                            const float* __restrict__ bet, float* __restrict__ out, int H,
                            const float* __restrict__ agg, const float* __restrict__ denom) {
    int v = (blockIdx.x * blockDim.x + threadIdx.x) >> 5;
    int lane = threadIdx.x & 31;
    if (v >= NN) return;
    float vals[4];
    int c0 = lane * 4;
    if (H == 2) {
        float i0 = 1.f / fmaxf(denom[v * 2 + 0], 1e-16f);
        float i1 = 1.f / fmaxf(denom[v * 2 + 1], 1e-16f);
        float4 a = ((const float4*)(agg + (size_t)v * 256))[lane];
        float4 b = ((const float4*)(agg + (size_t)v * 256 + 128))[lane];
        vals[0] = 0.5f * (a.x * i0 + b.x * i1) + bias[c0 + 0];
        vals[1] = 0.5f * (a.y * i0 + b.y * i1) + bias[c0 + 1];
        vals[2] = 0.5f * (a.z * i0 + b.z * i1) + bias[c0 + 2];
        vals[3] = 0.5f * (a.w * i0 + b.w * i1) + bias[c0 + 3];
    } else {
        float i0 = 1.f / fmaxf(denom[v], 1e-16f);
        float4 a = ((const float4*)(agg + (size_t)v * 128))[lane];
        vals[0] = a.x * i0 + bias[c0 + 0];
        vals[1] = a.y * i0 + bias[c0 + 1];
        vals[2] = a.z * i0 + bias[c0 + 2];
        vals[3] = a.w * i0 + bias[c0 + 3];
    }
    float mu = warp_sum(vals[0] + vals[1] + vals[2] + vals[3]) * (1.f / 128.f);
    float sq = 0.f;
#pragma unroll
    for (int j = 0; j < 4; j++) { float dlt = vals[j] - mu; sq += dlt * dlt; }
    float var = warp_sum(sq) * (1.f / 128.f);
    float rstd = rsqrtf(var + 1e-5f);
#pragma unroll
    for (int j = 0; j < 4; j++) {
        int c = c0 + j;
        float y = (vals[j] - mu) * rstd * gam[c] + bet[c];
        out[(size_t)v * 128 + c] = y > 0.f ? y : (expf(y) - 1.f);
    }
}

// ---------------- host ----------------
static float* sym(const void* s) { void* p = nullptr; cudaGetSymbolAddress(&p, s); return (float*)p; }

extern "C" void kernel_launch(void* const* d_in, const int* in_sizes, int n_in,
                              void* d_out, int out_size) {
    const float* node_stats = (const float*)d_in[1];
    const int*   edge_index = (const int*)d_in[2];
    const float* edge_attr  = (const float*)d_in[3];
    const float* epw = (const float*)d_in[4];
    const float* epb = (const float*)d_in[5];
    const float* g1wl = (const float*)d_in[6];
    const float* g1wr = (const float*)d_in[7];
    const float* g1we = (const float*)d_in[8];
    const float* g1att = (const float*)d_in[9];
    const float* g1b = (const float*)d_in[10];
    const float* n1g = (const float*)d_in[11];
    const float* n1b = (const float*)d_in[12];
    const float* g2wl = (const float*)d_in[13];
    const float* g2wr = (const float*)d_in[14];
    const float* g2we = (const float*)d_in[15];
    const float* g2att = (const float*)d_in[16];
    const float* g2b = (const float*)d_in[17];
    const float* n2g = (const float*)d_in[18];
    const float* n2b = (const float*)d_in[19];
    const float* c1w = (const float*)d_in[20];
    const float* c1b = (const float*)d_in[21];
    const float* c2w = (const float*)d_in[22];
    const float* c2b = (const float*)d_in[23];
    const float* c3w = (const float*)d_in[24];
    const float* c3b = (const float*)d_in[25];

    const int* src = edge_index;
    const int* dst = edge_index + EE;

    float* p_xi   = sym(g_xi);
    float* p_xlr  = sym(g_xlr);
    float* p_la   = sym(g_la);
    float* p_h1   = sym(g_h1);
    float* p_h2   = sym(g_h2);
    float* p_wcat = sym(g_wcat);
    float* p_agg1 = sym(g_agg1);
    float* p_agg2 = sym(g_agg2);
    float* p_den1 = sym(g_den1);
    float* p_den2 = sym(g_den2);

    const int T = 256;
    dim3 gNwarp((NN + 7) / 8);
    const int MB_E = EE / 128;                 // 3125
    const int MB_N = (NN + 127) / 128;         // 391
    const int NB_L = (E2 + 127) / 128;         // 3516

    // ---- Stage A ----
    k_zero_all<<<2048, T>>>();
    gemm128<1, 0, 1><<<dim3(1, MB_E), 512>>>(edge_attr, 64, 64, epw, epb, nullptr, EE, 128,
                                             src, dst, nullptr, edge_attr);
    k_build_xi<<<1024, T>>>(node_stats);

    // ---- GAT layer 1 (H=2) ----
    k_catw<<<(258 * 512 + T - 1) / T, T>>>(g1wl, g1wr, 258, 256);
    gemm128<0, 0, 0><<<dim3(4, MB_N), 512>>>(p_xi, XI_LD, 258, p_wcat, nullptr, p_xlr, NN, 512,
                                             nullptr, nullptr, nullptr, nullptr);
    k_gat_edge<2><<<NB_L, T>>>(edge_attr, p_la, g1we, g1att, p_xlr, src, dst, p_agg1, p_den1);
    k_gat_final<<<gNwarp, T>>>(g1b, n1g, n1b, p_h1, 2, p_agg1, p_den1);

    // ---- GAT layer 2 (H=1) ----
    k_catw<<<(128 * 256 + T - 1) / T, T>>>(g2wl, g2wr, 128, 128);
    gemm128<0, 0, 0><<<dim3(2, MB_N), 512>>>(p_h1, 128, 128, p_wcat, nullptr, p_xlr, NN, 256,
                                             nullptr, nullptr, nullptr, nullptr);
    k_gat_edge<1><<<NB_L, T>>>(edge_attr, p_la, g2we, g2att, p_xlr, src, dst, p_agg2, p_den2);
    k_gat_final<<<gNwarp, T>>>(g2b, n2g, n2b, p_h2, 1, p_agg2, p_den2);

    // ---- Classifier: fully fused c1+c2+c3 ----
    gemm_c1c2c3<<<MB_E, 512>>>(c1w, c1b, c2w, c2b, c3w, c3b,
                               src, dst, p_h2, edge_attr, (float*)d_out);
}

// round 6
// speedup vs baseline: 4.1346x; 1.1640x over previous
#include <cuda_runtime.h>
#include <math.h>

#define NN 50000
#define EE 400000
#define E2 (EE + 50000)
#define XI_LD 264

// ---------------- scratch ----------------
__device__ float g_xi[NN * XI_LD + 64];
__device__ float g_xlr[NN * 512 + 64];   // xl|xr; reused as P12 for classifier
__device__ float g_la[NN * 64 + 64];
__device__ float g_xout[NN * 128];
__device__ float g_xin[NN * 128];
__device__ float g_lsum[NN * 64];
__device__ float g_degs[NN];
__device__ float g_degd[NN];
__device__ float g_h1[NN * 128 + 64];
__device__ float g_h2[NN * 128 + 64];
__device__ float g_logit[E2 * 2];
__device__ float g_wcat[264 * 512];
__device__ int   g_csr_off[NN + 1];
__device__ int   g_csr_pos[NN];
__device__ int   g_csr_edge[E2];
__device__ int   g_bsum[64];

// ---------------- helpers ----------------
__device__ __forceinline__ float lrelu02(float x) { return x > 0.f ? x : 0.2f * x; }

__device__ __forceinline__ float warp_sum(float v) {
#pragma unroll
    for (int o = 16; o; o >>= 1) v += __shfl_xor_sync(0xffffffffu, v, o);
    return v;
}
__device__ __forceinline__ int warp_sum_i(int v) {
#pragma unroll
    for (int o = 16; o; o >>= 1) v += __shfl_xor_sync(0xffffffffu, v, o);
    return v;
}

__device__ __forceinline__ void redv2(float* p, float a, float b) {
    asm volatile("red.global.add.v2.f32 [%0], {%1, %2};" :: "l"(p), "f"(a), "f"(b) : "memory");
}
__device__ __forceinline__ void redv4(float* p, float a, float b, float c, float d) {
    asm volatile("red.global.add.v4.f32 [%0], {%1, %2, %3, %4};"
                 :: "l"(p), "f"(a), "f"(b), "f"(c), "f"(d) : "memory");
}

__device__ __forceinline__ unsigned f2tf(float x) {
    unsigned u;
    asm("cvt.rna.tf32.f32 %0, %1;" : "=r"(u) : "f"(x));
    return u;
}

__device__ __forceinline__ void mma_tf32(float c[4], const unsigned a[4], const unsigned b[2]) {
    asm volatile(
        "mma.sync.aligned.m16n8k8.row.col.f32.tf32.tf32.f32 "
        "{%0,%1,%2,%3},{%4,%5,%6,%7},{%8,%9},{%0,%1,%2,%3};"
        : "+f"(c[0]), "+f"(c[1]), "+f"(c[2]), "+f"(c[3])
        : "r"(a[0]), "r"(a[1]), "r"(a[2]), "r"(a[3]), "r"(b[0]), "r"(b[1]));
}

// ======== wide TF32 GEMM: BM=128 BN=128 BK=32, 512 threads ========
template <int ACT, int EPI>
__global__ __launch_bounds__(512, 1)
void gemm128(const float* __restrict__ A, int lda, int K,
             const float* __restrict__ B,
             const float* __restrict__ bias,
             float* __restrict__ C, int M, int N,
             const int* __restrict__ gsrc, const int* __restrict__ gdst,
             const float* __restrict__ ea) {
    __shared__ unsigned As[128][36];
    __shared__ unsigned Bs[32][136];
    int tid = threadIdx.x;
    int warp = tid >> 5, lane = tid & 31;
    int wm = warp & 3, wn = warp >> 2;
    int rowBase = blockIdx.y * 128;
    int colBase = blockIdx.x * 128;
    int q = lane >> 2, r4 = lane & 3;

    float acc[2][4][4];
#pragma unroll
    for (int mt = 0; mt < 2; mt++)
#pragma unroll
        for (int nt = 0; nt < 4; nt++)
#pragma unroll
            for (int j = 0; j < 4; j++) acc[mt][nt][j] = 0.f;

    float4 pa[2], pb[2];
    auto loadA = [&](int k0) {
#pragma unroll
        for (int i = 0; i < 2; i++) {
            int idx = tid + i * 512;
            int row = idx >> 3, kk = (idx & 7) * 4;
            int gk = k0 + kk;
            float4 v = make_float4(0.f, 0.f, 0.f, 0.f);
            int gr = rowBase + row;
            if (gr < M && gk < lda) v = *(const float4*)(A + (size_t)gr * lda + gk);
            pa[i] = v;
        }
    };
    auto loadB = [&](int k0) {
#pragma unroll
        for (int i = 0; i < 2; i++) {
            int idx = tid + i * 512;
            int kk = idx >> 5, cc = (idx & 31) * 4;
            int gk = k0 + kk;
            float4 v = make_float4(0.f, 0.f, 0.f, 0.f);
            if (gk < K) v = *(const float4*)(B + (size_t)gk * N + colBase + cc);
            pb[i] = v;
        }
    };
    auto stsAB = [&]() {
#pragma unroll
        for (int i = 0; i < 2; i++) {
            int idx = tid + i * 512;
            int row = idx >> 3, kk = (idx & 7) * 4;
            uint4 t;
            t.x = f2tf(pa[i].x); t.y = f2tf(pa[i].y); t.z = f2tf(pa[i].z); t.w = f2tf(pa[i].w);
            *(uint4*)&As[row][kk] = t;
            int kb = idx >> 5, cc = (idx & 31) * 4;
            uint4 u;
            u.x = f2tf(pb[i].x); u.y = f2tf(pb[i].y); u.z = f2tf(pb[i].z); u.w = f2tf(pb[i].w);
            *(uint4*)&Bs[kb][cc] = u;
        }
    };

    loadA(0); loadB(0);
    for (int k0 = 0; k0 < K; k0 += 32) {
        stsAB();
        __syncthreads();
        if (k0 + 32 < K) { loadA(k0 + 32); loadB(k0 + 32); }
#pragma unroll
        for (int ks = 0; ks < 4; ks++) {
            int kb = ks * 8;
            unsigned af[2][4], bf[4][2];
#pragma unroll
            for (int mt = 0; mt < 2; mt++) {
                int r0 = wm * 32 + mt * 16 + q;
                af[mt][0] = As[r0][kb + r4];
                af[mt][1] = As[r0 + 8][kb + r4];
                af[mt][2] = As[r0][kb + r4 + 4];
                af[mt][3] = As[r0 + 8][kb + r4 + 4];
            }
#pragma unroll
            for (int nt = 0; nt < 4; nt++) {
                int c0 = wn * 32 + nt * 8 + q;
                bf[nt][0] = Bs[kb + r4][c0];
                bf[nt][1] = Bs[kb + r4 + 4][c0];
            }
#pragma unroll
            for (int mt = 0; mt < 2; mt++)
#pragma unroll
                for (int nt = 0; nt < 4; nt++) mma_tf32(acc[mt][nt], af[mt], bf[nt]);
        }
        __syncthreads();
    }

    if (EPI == 0) {
#pragma unroll
        for (int mt = 0; mt < 2; mt++) {
            int gr0 = rowBase + wm * 32 + mt * 16 + q;
            int gr1 = gr0 + 8;
#pragma unroll
            for (int nt = 0; nt < 4; nt++) {
                int gc = colBase + wn * 32 + nt * 8 + r4 * 2;
                float2 bv = make_float2(0.f, 0.f);
                if (bias) bv = *(const float2*)(bias + gc);
                float o0 = acc[mt][nt][0] + bv.x, o1 = acc[mt][nt][1] + bv.y;
                float o2 = acc[mt][nt][2] + bv.x, o3 = acc[mt][nt][3] + bv.y;
                if (ACT == 1) {
                    o0 = fmaxf(o0, 0.f); o1 = fmaxf(o1, 0.f);
                    o2 = fmaxf(o2, 0.f); o3 = fmaxf(o3, 0.f);
                }
                if (gr0 < M) *(float2*)(C + (size_t)gr0 * N + gc) = make_float2(o0, o1);
                if (gr1 < M) *(float2*)(C + (size_t)gr1 * N + gc) = make_float2(o2, o3);
            }
        }
    } else {
        // emb scatter: relu(acc+bias) -> xout[src], xin[dst]
#pragma unroll
        for (int mt = 0; mt < 2; mt++) {
            int gr0 = rowBase + wm * 32 + mt * 16 + q;
            int gr1 = gr0 + 8;
            int s0 = __ldg(gsrc + gr0), d0 = __ldg(gdst + gr0);
            int s1 = __ldg(gsrc + gr1), d1 = __ldg(gdst + gr1);
#pragma unroll
            for (int nt = 0; nt < 4; nt++) {
                int gc = wn * 32 + nt * 8 + r4 * 2;
                float2 bv = *(const float2*)(bias + gc);
                float v0 = fmaxf(acc[mt][nt][0] + bv.x, 0.f);
                float v1 = fmaxf(acc[mt][nt][1] + bv.y, 0.f);
                float v2 = fmaxf(acc[mt][nt][2] + bv.x, 0.f);
                float v3 = fmaxf(acc[mt][nt][3] + bv.y, 0.f);
                redv2(&g_xout[(size_t)s0 * 128 + gc], v0, v1);
                redv2(&g_xin[(size_t)d0 * 128 + gc], v0, v1);
                redv2(&g_xout[(size_t)s1 * 128 + gc], v2, v3);
                redv2(&g_xin[(size_t)d1 * 128 + gc], v2, v3);
            }
        }
        int row = tid >> 2, part = tid & 3;
        int e = rowBase + row;
        int s = __ldg(gsrc + e), d = __ldg(gdst + e);
        const float4* pea = (const float4*)(ea + (size_t)e * 64) + part * 4;
#pragma unroll
        for (int j = 0; j < 4; j++) {
            float4 v = pea[j];
            redv4(&g_lsum[(size_t)d * 64 + part * 16 + j * 4], v.x, v.y, v.z, v.w);
        }
        if (part == 0) { atomicAdd(&g_degs[s], 1.f); atomicAdd(&g_degd[d], 1.f); }
    }
}

// ======== CSR build ========
__global__ void csr_blocksum() {
    int v = blockIdx.x * 1024 + threadIdx.x;
    int c = (v < NN) ? (int)(g_degd[v] + 0.5f) + 1 : 0;
    __shared__ int ws[32];
    int wsum = warp_sum_i(c);
    if ((threadIdx.x & 31) == 0) ws[threadIdx.x >> 5] = wsum;
    __syncthreads();
    if (threadIdx.x < 32) {
        int t = ws[threadIdx.x];
        t = warp_sum_i(t);
        if (threadIdx.x == 0) g_bsum[blockIdx.x] = t;
    }
}
__global__ void csr_scanblocks(int nb) {
    if (threadIdx.x == 0) {
        int run = 0;
        for (int b = 0; b < nb; b++) { int t = g_bsum[b]; g_bsum[b] = run; run += t; }
    }
}
__global__ void csr_finalize() {
    __shared__ int sm[1024];
    int tid = threadIdx.x;
    int v = blockIdx.x * 1024 + tid;
    int c = (v < NN) ? (int)(g_degd[v] + 0.5f) + 1 : 0;
    sm[tid] = c;
    __syncthreads();
    for (int o = 1; o < 1024; o <<= 1) {
        int t = (tid >= o) ? sm[tid - o] : 0;
        __syncthreads();
        sm[tid] += t;
        __syncthreads();
    }
    int incl = sm[tid];
    int base = g_bsum[blockIdx.x];
    if (v < NN) {
        int off = base + incl - c;
        g_csr_off[v] = off;
        g_csr_pos[v] = off;
        if (v == NN - 1) g_csr_off[NN] = base + incl;
    }
}
__global__ void csr_scatter(const int* __restrict__ dst) {
    int i = blockIdx.x * blockDim.x + threadIdx.x;
    if (i < EE) {
        int d = dst[i];
        int pos = atomicAdd(&g_csr_pos[d], 1);
        g_csr_edge[pos] = i;
    } else if (i < E2) {
        int v = i - EE;
        g_csr_edge[g_csr_off[v + 1] - 1] = i;   // self-loop last in segment
    }
}

// ======== ew GEMM + GATv2 logit (CSR edge order, logits only) ========
template <int H>
__global__ void k_gat_edge(const float* __restrict__ ea, const float* __restrict__ la,
                           const float* __restrict__ we, const float* __restrict__ att,
                           const float* __restrict__ xlr,
                           const int* __restrict__ src, const int* __restrict__ dst) {
    const int W = 2 * H * 128;
    const int XOFF = H * 128;
    const int NB = H * 128;
    __shared__ unsigned As[128][68];
    __shared__ unsigned Bs[32][72];
    __shared__ float sp[128][2];
    __shared__ float lg[H][128];
    int tid = threadIdx.x;
    int warp = tid >> 5, lane = tid & 31;
    int wm = warp & 3, wn = warp >> 2;
    int q = lane >> 2, r4 = lane & 3;
    int e0 = blockIdx.x * 128;

    for (int i = tid; i < H * 128; i += 256) lg[i >> 7][i & 127] = 0.f;

#pragma unroll
    for (int i = 0; i < 8; i++) {
        int idx = tid + i * 256;
        int row = idx >> 4, gc = (idx & 15) * 4;
        int p = e0 + row;
        float4 v = make_float4(0.f, 0.f, 0.f, 0.f);
        if (p < E2) {
            int e = __ldg(g_csr_edge + p);
            if (e < EE) v = *(const float4*)(ea + (size_t)e * 64 + gc);
            else        v = *(const float4*)(la + (size_t)(e - EE) * 64 + gc);
        }
        uint4 t;
        t.x = f2tf(v.x); t.y = f2tf(v.y); t.z = f2tf(v.z); t.w = f2tf(v.w);
        *(uint4*)&As[row][gc] = t;
    }
    int ss[2][2], dd[2][2];
    bool vld[2][2];
#pragma unroll
    for (int mt = 0; mt < 2; mt++)
#pragma unroll
        for (int hf = 0; hf < 2; hf++) {
            int p = e0 + wm * 32 + mt * 16 + hf * 8 + q;
            bool v = p < E2;
            vld[mt][hf] = v;
            if (!v) { ss[mt][hf] = 0; dd[mt][hf] = 0; }
            else {
                int e = __ldg(g_csr_edge + p);
                if (e < EE) { ss[mt][hf] = __ldg(src + e); dd[mt][hf] = __ldg(dst + e); }
                else { ss[mt][hf] = e - EE; dd[mt][hf] = e - EE; }
            }
        }
    __syncthreads();

    for (int strip = 0; strip < 2 * H; strip++) {
        float acc[2][4][4];
#pragma unroll
        for (int mt = 0; mt < 2; mt++)
#pragma unroll
            for (int nt = 0; nt < 4; nt++)
#pragma unroll
                for (int j = 0; j < 4; j++) acc[mt][nt][j] = 0.f;

        for (int kt = 0; kt < 2; kt++) {
            __syncthreads();
#pragma unroll
            for (int i = 0; i < 2; i++) {
                int idx = tid + i * 256;
                int kk = idx >> 4, cc = (idx & 15) * 4;
                float4 v = *(const float4*)(we + (size_t)(kt * 32 + kk) * NB + strip * 64 + cc);
                uint4 t;
                t.x = f2tf(v.x); t.y = f2tf(v.y); t.z = f2tf(v.z); t.w = f2tf(v.w);
                *(uint4*)&Bs[kk][cc] = t;
            }
            __syncthreads();
#pragma unroll
            for (int ks = 0; ks < 4; ks++) {
                int kb = ks * 8;
                unsigned af[2][4], bf[4][2];
#pragma unroll
                for (int mt = 0; mt < 2; mt++) {
                    int r0 = wm * 32 + mt * 16 + q;
                    int ka = kt * 32 + kb;
                    af[mt][0] = As[r0][ka + r4];
                    af[mt][1] = As[r0 + 8][ka + r4];
                    af[mt][2] = As[r0][ka + r4 + 4];
                    af[mt][3] = As[r0 + 8][ka + r4 + 4];
                }
#pragma unroll
                for (int nt = 0; nt < 4; nt++) {
                    int c0 = wn * 32 + nt * 8 + q;
                    bf[nt][0] = Bs[kb + r4][c0];
                    bf[nt][1] = Bs[kb + r4 + 4][c0];
                }
#pragma unroll
                for (int mt = 0; mt < 2; mt++)
#pragma unroll
                    for (int nt = 0; nt < 4; nt++) mma_tf32(acc[mt][nt], af[mt], bf[nt]);
            }
        }

        int h = strip >> 1;
        float prow[2][2] = {{0.f, 0.f}, {0.f, 0.f}};
#pragma unroll
        for (int mt = 0; mt < 2; mt++) {
#pragma unroll
            for (int nt = 0; nt < 4; nt++) {
                int gc = strip * 64 + wn * 32 + nt * 8 + r4 * 2;
                int ch = gc & 127;
                float2 at = *(const float2*)(att + h * 128 + ch);
                if (vld[mt][0]) {
                    float2 xv = *(const float2*)(xlr + (size_t)ss[mt][0] * W + h * 128 + ch);
                    float2 rv = *(const float2*)(xlr + (size_t)dd[mt][0] * W + XOFF + h * 128 + ch);
                    prow[mt][0] += lrelu02(acc[mt][nt][0] + xv.x + rv.x) * at.x +
                                   lrelu02(acc[mt][nt][1] + xv.y + rv.y) * at.y;
                }
                if (vld[mt][1]) {
                    float2 xv = *(const float2*)(xlr + (size_t)ss[mt][1] * W + h * 128 + ch);
                    float2 rv = *(const float2*)(xlr + (size_t)dd[mt][1] * W + XOFF + h * 128 + ch);
                    prow[mt][1] += lrelu02(acc[mt][nt][2] + xv.x + rv.x) * at.x +
                                   lrelu02(acc[mt][nt][3] + xv.y + rv.y) * at.y;
                }
            }
        }
#pragma unroll
        for (int mt = 0; mt < 2; mt++)
#pragma unroll
            for (int hf = 0; hf < 2; hf++) {
                float p = prow[mt][hf];
                p += __shfl_xor_sync(0xffffffffu, p, 1);
                p += __shfl_xor_sync(0xffffffffu, p, 2);
                if (r4 == 0) sp[wm * 32 + mt * 16 + hf * 8 + q][wn] = p;
            }
        __syncthreads();
        if (tid < 128) lg[h][tid] += sp[tid][0] + sp[tid][1];
    }
    __syncthreads();
    if (tid < 128) {
        int p = e0 + tid;
        if (p < E2) {
#pragma unroll
            for (int h = 0; h < H; h++) g_logit[(size_t)p * H + h] = lg[h][tid];
        }
    }
}

// ======== warp-per-node: softmax-aggregate + heads mean + LN + ELU ========
template <int H>
__global__ void k_gat_gather(const float* __restrict__ xlr, const int* __restrict__ src,
                             const float* __restrict__ bias, const float* __restrict__ gam,
                             const float* __restrict__ bet, float* __restrict__ out) {
    const int W = 2 * H * 128;
    int v = (blockIdx.x * blockDim.x + threadIdx.x) >> 5;
    int lane = threadIdx.x & 31;
    if (v >= NN) return;
    int beg = g_csr_off[v], end = g_csr_off[v + 1];
    float acc[H][4];
    float den[H];
#pragma unroll
    for (int h = 0; h < H; h++) {
        den[h] = 0.f;
#pragma unroll
        for (int j = 0; j < 4; j++) acc[h][j] = 0.f;
    }
    for (int p = beg; p < end; p++) {
        int e = __ldg(g_csr_edge + p);
        int s = (e < EE) ? __ldg(src + e) : v;
#pragma unroll
        for (int h = 0; h < H; h++) {
            float a = expf(__ldg(g_logit + (size_t)p * H + h));
            den[h] += a;
            float4 x = ((const float4*)(xlr + (size_t)s * W + h * 128))[lane];
            acc[h][0] += a * x.x; acc[h][1] += a * x.y;
            acc[h][2] += a * x.z; acc[h][3] += a * x.w;
        }
    }
    float vals[4];
    int c0 = lane * 4;
    if (H == 2) {
        float i0 = 1.f / fmaxf(den[0], 1e-16f);
        float i1 = 1.f / fmaxf(den[1], 1e-16f);
#pragma unroll
        for (int j = 0; j < 4; j++)
            vals[j] = 0.5f * (acc[0][j] * i0 + acc[H - 1][j] * i1) + bias[c0 + j];
    } else {
        float i0 = 1.f / fmaxf(den[0], 1e-16f);
#pragma unroll
        for (int j = 0; j < 4; j++) vals[j] = acc[0][j] * i0 + bias[c0 + j];
    }
    float mu = warp_sum(vals[0] + vals[1] + vals[2] + vals[3]) * (1.f / 128.f);
    float sq = 0.f;
#pragma unroll
    for (int j = 0; j < 4; j++) { float dlt = vals[j] - mu; sq += dlt * dlt; }
    float var = warp_sum(sq) * (1.f / 128.f);
    float rstd = rsqrtf(var + 1e-5f);
#pragma unroll
    for (int j = 0; j < 4; j++) {
        int c = c0 + j;
        float y = (vals[j] - mu) * rstd * gam[c] + bet[c];
        out[(size_t)v * 128 + c] = y > 0.f ? y : (expf(y) - 1.f);
    }
}

// ======== classifier edge kernel: ea@c1w_e + P1[s]+P2[d] -> relu -> c2 -> c3 ========
__global__ __launch_bounds__(512, 1)
void k_cls_edge(const float* __restrict__ c1w, const float* __restrict__ c1b,
                const float* __restrict__ c2w, const float* __restrict__ c2b,
                const float* __restrict__ w3, const float* __restrict__ b3,
                const int* __restrict__ gsrc, const int* __restrict__ gdst,
                const float* __restrict__ p12, const float* __restrict__ ea,
                float* __restrict__ out) {
    __shared__ unsigned As[128][36];
    __shared__ unsigned Bs[32][136];
    __shared__ float sp[128][4];
    int tid = threadIdx.x;
    int warp = tid >> 5, lane = tid & 31;
    int wm = warp & 3, wn = warp >> 2;
    int rowBase = blockIdx.x * 128;
    int q = lane >> 2, r4 = lane & 3;

    // ---- stage 1: ea(128x64) @ c1w[256:320] (64x128) ----
    float acc[2][4][4];
#pragma unroll
    for (int mt = 0; mt < 2; mt++)
#pragma unroll
        for (int nt = 0; nt < 4; nt++)
#pragma unroll
            for (int j = 0; j < 4; j++) acc[mt][nt][j] = 0.f;

    for (int k0 = 0; k0 < 64; k0 += 32) {
#pragma unroll
        for (int i = 0; i < 2; i++) {
            int idx = tid + i * 512;
            int row = idx >> 3, kk = (idx & 7) * 4;
            float4 v = *(const float4*)(ea + (size_t)(rowBase + row) * 64 + k0 + kk);
            uint4 t;
            t.x = f2tf(v.x); t.y = f2tf(v.y); t.z = f2tf(v.z); t.w = f2tf(v.w);
            *(uint4*)&As[row][kk] = t;
        }
#pragma unroll
        for (int i = 0; i < 2; i++) {
            int idx = tid + i * 512;
            int kk = idx >> 5, cc = (idx & 31) * 4;
            float4 v = *(const float4*)(c1w + (size_t)(256 + k0 + kk) * 128 + cc);
            uint4 t;
            t.x = f2tf(v.x); t.y = f2tf(v.y); t.z = f2tf(v.z); t.w = f2tf(v.w);
            *(uint4*)&Bs[kk][cc] = t;
        }
        __syncthreads();
#pragma unroll
        for (int ks = 0; ks < 4; ks++) {
            int kb = ks * 8;
            unsigned af[2][4], bf[4][2];
#pragma unroll
            for (int mt = 0; mt < 2; mt++) {
                int r0 = wm * 32 + mt * 16 + q;
                af[mt][0] = As[r0][kb + r4];
                af[mt][1] = As[r0 + 8][kb + r4];
                af[mt][2] = As[r0][kb + r4 + 4];
                af[mt][3] = As[r0 + 8][kb + r4 + 4];
            }
#pragma unroll
            for (int nt = 0; nt < 4; nt++) {
                int c0 = wn * 32 + nt * 8 + q;
                bf[nt][0] = Bs[kb + r4][c0];
                bf[nt][1] = Bs[kb + r4 + 4][c0];
            }
#pragma unroll
            for (int mt = 0; mt < 2; mt++)
#pragma unroll
                for (int nt = 0; nt < 4; nt++) mma_tf32(acc[mt][nt], af[mt], bf[nt]);
        }
        __syncthreads();
    }

    int sA[2], dA[2], sB[2], dB[2];
#pragma unroll
    for (int mt = 0; mt < 2; mt++) {
        int gr0 = rowBase + wm * 32 + mt * 16 + q;
        sA[mt] = __ldg(gsrc + gr0); dA[mt] = __ldg(gdst + gr0);
        sB[mt] = __ldg(gsrc + gr0 + 8); dB[mt] = __ldg(gdst + gr0 + 8);
    }

    // ---- stage 2: c1 = relu(acc + P1[s] + P2[d] + c1b); c2 accumulate over 4 chunks ----
    float acc2[2][2][4];
#pragma unroll
    for (int mt = 0; mt < 2; mt++)
#pragma unroll
        for (int nt = 0; nt < 2; nt++)
#pragma unroll
            for (int j = 0; j < 4; j++) acc2[mt][nt][j] = 0.f;

    for (int kc = 0; kc < 4; kc++) {
        __syncthreads();
        if (wn == kc) {
#pragma unroll
            for (int mt = 0; mt < 2; mt++) {
                int r0 = wm * 32 + mt * 16 + q, r1 = r0 + 8;
#pragma unroll
                for (int nt = 0; nt < 4; nt++) {
                    int lc = nt * 8 + r4 * 2;
                    int gc = kc * 32 + lc;
                    float2 bv = *(const float2*)(c1b + gc);
                    float2 pa = *(const float2*)(p12 + (size_t)sA[mt] * 256 + gc);
                    float2 pb = *(const float2*)(p12 + (size_t)dA[mt] * 256 + 128 + gc);
                    As[r0][lc]     = f2tf(fmaxf(acc[mt][nt][0] + bv.x + pa.x + pb.x, 0.f));
                    As[r0][lc + 1] = f2tf(fmaxf(acc[mt][nt][1] + bv.y + pa.y + pb.y, 0.f));
                    float2 pc = *(const float2*)(p12 + (size_t)sB[mt] * 256 + gc);
                    float2 pd = *(const float2*)(p12 + (size_t)dB[mt] * 256 + 128 + gc);
                    As[r1][lc]     = f2tf(fmaxf(acc[mt][nt][2] + bv.x + pc.x + pd.x, 0.f));
                    As[r1][lc + 1] = f2tf(fmaxf(acc[mt][nt][3] + bv.y + pc.y + pd.y, 0.f));
                }
            }
        }
        {
            int kk = tid >> 4, cc = (tid & 15) * 4;
            float4 v = *(const float4*)(c2w + (size_t)(kc * 32 + kk) * 64 + cc);
            uint4 t;
            t.x = f2tf(v.x); t.y = f2tf(v.y); t.z = f2tf(v.z); t.w = f2tf(v.w);
            *(uint4*)&Bs[kk][cc] = t;
        }
        __syncthreads();
#pragma unroll
        for (int ks = 0; ks < 4; ks++) {
            int kb = ks * 8;
            unsigned af[2][4], bf[2][2];
#pragma unroll
            for (int mt = 0; mt < 2; mt++) {
                int r0 = wm * 32 + mt * 16 + q;
                af[mt][0] = As[r0][kb + r4];
                af[mt][1] = As[r0 + 8][kb + r4];
                af[mt][2] = As[r0][kb + r4 + 4];
                af[mt][3] = As[r0 + 8][kb + r4 + 4];
            }
#pragma unroll
            for (int nt = 0; nt < 2; nt++) {
                int c0 = wn * 16 + nt * 8 + q;
                bf[nt][0] = Bs[kb + r4][c0];
                bf[nt][1] = Bs[kb + r4 + 4][c0];
            }
#pragma unroll
            for (int mt = 0; mt < 2; mt++)
#pragma unroll
                for (int nt = 0; nt < 2; nt++) mma_tf32(acc2[mt][nt], af[mt], bf[nt]);
        }
    }

    // ---- stage 3: relu(c2 + c2b) . w3 + b3 ----
    float p0[2] = {0.f, 0.f}, p1[2] = {0.f, 0.f};
#pragma unroll
    for (int mt = 0; mt < 2; mt++) {
#pragma unroll
        for (int nt = 0; nt < 2; nt++) {
            int gc = wn * 16 + nt * 8 + r4 * 2;
            float2 bv = *(const float2*)(c2b + gc);
            float2 wv = *(const float2*)(w3 + gc);
            p0[mt] += fmaxf(acc2[mt][nt][0] + bv.x, 0.f) * wv.x +
                      fmaxf(acc2[mt][nt][1] + bv.y, 0.f) * wv.y;
            p1[mt] += fmaxf(acc2[mt][nt][2] + bv.x, 0.f) * wv.x +
                      fmaxf(acc2[mt][nt][3] + bv.y, 0.f) * wv.y;
        }
    }
    __syncthreads();
#pragma unroll
    for (int mt = 0; mt < 2; mt++) {
        float a = p0[mt], b = p1[mt];
        a += __shfl_xor_sync(0xffffffffu, a, 1); a += __shfl_xor_sync(0xffffffffu, a, 2);
        b += __shfl_xor_sync(0xffffffffu, b, 1); b += __shfl_xor_sync(0xffffffffu, b, 2);
        if (r4 == 0) {
            sp[wm * 32 + mt * 16 + q][wn] = a;
            sp[wm * 32 + mt * 16 + 8 + q][wn] = b;
        }
    }
    __syncthreads();
    if (tid < 128)
        out[rowBase + tid] = sp[tid][0] + sp[tid][1] + sp[tid][2] + sp[tid][3] + b3[0];
}

// ---------------- small kernels ----------------
__global__ void k_zero_all() {
    int i0 = blockIdx.x * blockDim.x + threadIdx.x;
    int stride = gridDim.x * blockDim.x;
    for (int t = i0; t < NN * 128; t += stride) { g_xout[t] = 0.f; g_xin[t] = 0.f; }
    for (int t = i0; t < NN * 64; t += stride) g_lsum[t] = 0.f;
    for (int t = i0; t < NN; t += stride) { g_degs[t] = 0.f; g_degd[t] = 0.f; }
}

__global__ void k_build_xi(const float* __restrict__ node_stats) {
    int i0 = blockIdx.x * blockDim.x + threadIdx.x;
    int stride = gridDim.x * blockDim.x;
    for (int t = i0; t < NN * 128; t += stride) {
        int v = t >> 7, c = t & 127;
        g_xi[(size_t)v * XI_LD + c] = g_xout[t] / fmaxf(g_degs[v], 1.f);
        g_xi[(size_t)v * XI_LD + 128 + c] = g_xin[t] / fmaxf(g_degd[v], 1.f);
    }
    for (int t = i0; t < NN * 64; t += stride) {
        int v = t >> 6;
        g_la[t] = g_lsum[t] / fmaxf(g_degd[v], 1.f);
    }
    for (int t = i0; t < NN * 8; t += stride) {
        int v = t >> 3, c = t & 7;
        g_xi[(size_t)v * XI_LD + 256 + c] = (c < 2) ? node_stats[v * 2 + c] : 0.f;
    }
}

__global__ void k_catw(const float* __restrict__ wl, const float* __restrict__ wr,
                       int K, int N1) {
    int i = blockIdx.x * blockDim.x + threadIdx.x;
    int tot = K * 2 * N1;
    if (i >= tot) return;
    int k = i / (2 * N1), j = i - k * 2 * N1;
    g_wcat[i] = (j < N1) ? wl[k * N1 + j] : wr[k * N1 + (j - N1)];
}

// ---------------- host ----------------
static float* sym(const void* s) { void* p = nullptr; cudaGetSymbolAddress(&p, s); return (float*)p; }

extern "C" void kernel_launch(void* const* d_in, const int* in_sizes, int n_in,
                              void* d_out, int out_size) {
    const float* node_stats = (const float*)d_in[1];
    const int*   edge_index = (const int*)d_in[2];
    const float* edge_attr  = (const float*)d_in[3];
    const float* epw = (const float*)d_in[4];
    const float* epb = (const float*)d_in[5];
    const float* g1wl = (const float*)d_in[6];
    const float* g1wr = (const float*)d_in[7];
    const float* g1we = (const float*)d_in[8];
    const float* g1att = (const float*)d_in[9];
    const float* g1b = (const float*)d_in[10];
    const float* n1g = (const float*)d_in[11];
    const float* n1b = (const float*)d_in[12];
    const float* g2wl = (const float*)d_in[13];
    const float* g2wr = (const float*)d_in[14];
    const float* g2we = (const float*)d_in[15];
    const float* g2att = (const float*)d_in[16];
    const float* g2b = (const float*)d_in[17];
    const float* n2g = (const float*)d_in[18];
    const float* n2b = (const float*)d_in[19];
    const float* c1w = (const float*)d_in[20];
    const float* c1b = (const float*)d_in[21];
    const float* c2w = (const float*)d_in[22];
    const float* c2b = (const float*)d_in[23];
    const float* c3w = (const float*)d_in[24];
    const float* c3b = (const float*)d_in[25];

    const int* src = edge_index;
    const int* dst = edge_index + EE;

    float* p_xi   = sym(g_xi);
    float* p_xlr  = sym(g_xlr);
    float* p_la   = sym(g_la);
    float* p_h1   = sym(g_h1);
    float* p_h2   = sym(g_h2);
    float* p_wcat = sym(g_wcat);

    const int T = 256;
    dim3 gNwarp((NN + 7) / 8);
    const int MB_E = EE / 128;                 // 3125
    const int MB_N = (NN + 127) / 128;         // 391
    const int NB_L = (E2 + 127) / 128;         // 3516
    const int NB_SCAN = (NN + 1023) / 1024;    // 49

    // ---- Stage A: zero, emb GEMM + scatter, xi, CSR build ----
    k_zero_all<<<2048, T>>>();
    gemm128<1, 1><<<dim3(1, MB_E), 512>>>(edge_attr, 64, 64, epw, epb, nullptr, EE, 128,
                                          src, dst, edge_attr);
    k_build_xi<<<1024, T>>>(node_stats);
    csr_blocksum<<<NB_SCAN, 1024>>>();
    csr_scanblocks<<<1, 32>>>(NB_SCAN);
    csr_finalize<<<NB_SCAN, 1024>>>();
    csr_scatter<<<(E2 + T - 1) / T, T>>>(dst);

    // ---- GAT layer 1 (H=2) ----
    k_catw<<<(258 * 512 + T - 1) / T, T>>>(g1wl, g1wr, 258, 256);
    gemm128<0, 0><<<dim3(4, MB_N), 512>>>(p_xi, XI_LD, 258, p_wcat, nullptr, p_xlr, NN, 512,
                                          nullptr, nullptr, nullptr);
    k_gat_edge<2><<<NB_L, T>>>(edge_attr, p_la, g1we, g1att, p_xlr, src, dst);
    k_gat_gather<2><<<gNwarp, T>>>(p_xlr, src, g1b, n1g, n1b, p_h1);

    // ---- GAT layer 2 (H=1) ----
    k_catw<<<(128 * 256 + T - 1) / T, T>>>(g2wl, g2wr, 128, 128);
    gemm128<0, 0><<<dim3(2, MB_N), 512>>>(p_h1, 128, 128, p_wcat, nullptr, p_xlr, NN, 256,
                                          nullptr, nullptr, nullptr);
    k_gat_edge<1><<<NB_L, T>>>(edge_attr, p_la, g2we, g2att, p_xlr, src, dst);
    k_gat_gather<1><<<gNwarp, T>>>(p_xlr, src, g2b, n2g, n2b, p_h2);

    // ---- Classifier: P12 = h2 @ [c1w_src | c1w_dst], then fused edge kernel ----
    k_catw<<<(128 * 256 + T - 1) / T, T>>>(c1w, c1w + 128 * 128, 128, 128);
    gemm128<0, 0><<<dim3(2, MB_N), 512>>>(p_h2, 128, 128, p_wcat, nullptr, p_xlr, NN, 256,
                                          nullptr, nullptr, nullptr);
    k_cls_edge<<<MB_E, 512>>>(c1w, c1b, c2w, c2b, c3w, c3b,
                              src, dst, p_xlr, edge_attr, (float*)d_out);
}